// round 10
// baseline (speedup 1.0000x reference)
#include <cuda_runtime.h>
#include <cuda_bf16.h>
#include <math.h>
#include <stdint.h>

// Problem constants
constexpr int CB  = 2;
constexpr int CS  = 2048;
constexpr int CD  = 1024;
constexpr int CH  = 16;
constexpr int CHD = 64;
constexpr int MT  = CB * CS;  // 4096

// Scratch (allocation-free rule: static __device__ arrays)
__device__ __align__(256) float g_q[MT * CD];
__device__ __align__(256) float g_k[MT * CD];
__device__ __align__(256) float g_v[MT * CD];
__device__ __align__(256) float g_vals[MT * CD];

// ---------------------------------------------------------------------------
// TF32 helpers
// ---------------------------------------------------------------------------
__device__ __forceinline__ uint32_t f2tf32(float x) {
    uint32_t u;
    asm("cvt.rna.tf32.f32 %0, %1;" : "=r"(u) : "f"(x));
    return u;
}

__device__ __forceinline__ void mma_tf32(float c[4], const uint32_t a[4],
                                         const uint32_t b[2]) {
    asm volatile(
        "mma.sync.aligned.m16n8k8.row.col.f32.tf32.tf32.f32 "
        "{%0,%1,%2,%3}, {%4,%5,%6,%7}, {%8,%9}, {%0,%1,%2,%3};"
        : "+f"(c[0]), "+f"(c[1]), "+f"(c[2]), "+f"(c[3])
        : "r"(a[0]), "r"(a[1]), "r"(a[2]), "r"(a[3]), "r"(b[0]), "r"(b[1]));
}

__device__ __forceinline__ uint32_t smem_u32(const void* p) {
    uint32_t a;
    asm("{ .reg .u64 t; cvta.to.shared.u64 t, %1; cvt.u32.u64 %0, t; }"
        : "=r"(a) : "l"(p));
    return a;
}

__device__ __forceinline__ void cp16(uint32_t dst, const void* src) {
    asm volatile("cp.async.cg.shared.global [%0], [%1], 16;"
                 :: "r"(dst), "l"(src) : "memory");
}
#define CP_COMMIT() asm volatile("cp.async.commit_group;" ::: "memory")
#define CP_WAIT1()  asm volatile("cp.async.wait_group 1;" ::: "memory")

// ---------------------------------------------------------------------------
// TF32 tensor-core GEMM v6: cp.async 3-stage pipeline, BK=32, 256 threads
// (8 warps, 64x32 warp tiles — 16 warps/SM for latency hiding), raw-fp32
// smem, cvt at fragment load. C[M,N] = A[M,K] * W[K,N]. CTA tile 128x128.
// ---------------------------------------------------------------------------
constexpr int BM = 128, BN = 128;
constexpr int APAD = 36;                // words per A row (k32 + pad)
constexpr int BPAD = 136;               // words per B row (n128 + pad)
constexpr int ABYTES = BM * APAD * 4;   // 18432
constexpr int BBYTES = 32 * BPAD * 4;   // 17408
constexpr int STAGEB = ABYTES + BBYTES; // 35840
constexpr int GEMM_SMEM6 = 3 * STAGEB;  // 107520

__global__ __launch_bounds__(256) void sgemm_tf32_v6(
    const float* __restrict__ A0, const float* __restrict__ A1,
    const float* __restrict__ A2, const float* __restrict__ W0,
    const float* __restrict__ W1, const float* __restrict__ W2,
    float* __restrict__ C0, float* __restrict__ C1, float* __restrict__ C2,
    int M, int N, int K) {
    extern __shared__ char smem[];
    const uint32_t sb = smem_u32(smem);

    const int z = blockIdx.z;
    const float* A = (z == 0) ? A0 : (z == 1) ? A1 : A2;
    const float* W = (z == 0) ? W0 : (z == 1) ? W1 : W2;
    float*       C = (z == 0) ? C0 : (z == 1) ? C1 : C2;

    const int t    = threadIdx.x;
    const int lane = t & 31;
    const int warp = t >> 5;
    const int wm   = warp & 1;   // m offset 0/64
    const int wn   = warp >> 1;  // n offset 0..3 (x32)
    const int gid  = lane >> 2;  // 0..7
    const int tg   = lane & 3;   // 0..3

    const int m0b = blockIdx.y * BM;
    const int n0b = blockIdx.x * BN;

    const int NC = K / 32;

    float c[4][4][4];
#pragma unroll
    for (int mt = 0; mt < 4; ++mt)
#pragma unroll
        for (int nt = 0; nt < 4; ++nt)
#pragma unroll
            for (int i = 0; i < 4; ++i) c[mt][nt][i] = 0.f;

    // async fill of one stage: A 128x32 (1024 16B segs) + B 32x128 (1024 segs)
    auto issue = [&](int ck, int s) {
        const int kn = ck * 32;
        const uint32_t abase = sb + s * STAGEB;
        const uint32_t bbase = abase + ABYTES;
#pragma unroll
        for (int i = 0; i < 4; ++i) {
            const int ci = t + i * 256;
            const int ar = ci >> 3, as = ci & 7;
            cp16(abase + (ar * APAD + as * 4) * 4,
                 &A[(size_t)(m0b + ar) * K + kn + as * 4]);
            const int br = ci >> 5, bs = ci & 31;
            cp16(bbase + (br * BPAD + bs * 4) * 4,
                 &W[(size_t)(kn + br) * N + n0b + bs * 4]);
        }
        CP_COMMIT();
    };

    issue(0, 0);
    issue(1, 1);

    for (int ck = 0; ck < NC; ++ck) {
        CP_WAIT1();
        __syncthreads();
        if (ck + 2 < NC) issue(ck + 2, (ck + 2) % 3);

        const int s = ck % 3;
        const float* As = (const float*)(smem + s * STAGEB);
        const float* Bs = (const float*)(smem + s * STAGEB + ABYTES);

#pragma unroll
        for (int kk = 0; kk < 32; kk += 8) {
            uint32_t af[4][4], bf[4][2];
#pragma unroll
            for (int mt = 0; mt < 4; ++mt) {
                const int mm = wm * 64 + mt * 16 + gid;
                af[mt][0] = f2tf32(As[mm * APAD + kk + tg]);
                af[mt][1] = f2tf32(As[(mm + 8) * APAD + kk + tg]);
                af[mt][2] = f2tf32(As[mm * APAD + kk + tg + 4]);
                af[mt][3] = f2tf32(As[(mm + 8) * APAD + kk + tg + 4]);
            }
#pragma unroll
            for (int nt = 0; nt < 4; ++nt) {
                const int nn = wn * 32 + nt * 8 + gid;
                bf[nt][0] = f2tf32(Bs[(kk + tg) * BPAD + nn]);
                bf[nt][1] = f2tf32(Bs[(kk + tg + 4) * BPAD + nn]);
            }
#pragma unroll
            for (int mt = 0; mt < 4; ++mt)
#pragma unroll
                for (int nt = 0; nt < 4; ++nt) mma_tf32(c[mt][nt], af[mt], bf[nt]);
        }
    }

    // epilogue
#pragma unroll
    for (int mt = 0; mt < 4; ++mt) {
        const int r0 = m0b + wm * 64 + mt * 16 + gid;
#pragma unroll
        for (int nt = 0; nt < 4; ++nt) {
            const int cc = n0b + wn * 32 + nt * 8 + tg * 2;
            *(float2*)&C[(size_t)r0 * N + cc]       = make_float2(c[mt][nt][0], c[mt][nt][1]);
            *(float2*)&C[(size_t)(r0 + 8) * N + cc] = make_float2(c[mt][nt][2], c[mt][nt][3]);
        }
    }
}

// ---------------------------------------------------------------------------
// RoPE (bf16 cos/sin tables, matching reference) + RMSNorm, in place.
// blockIdx.y selects q (0) or k (1).
// ---------------------------------------------------------------------------
__global__ __launch_bounds__(256) void rope_rms_kernel(float* __restrict__ xq,
                                                       float* __restrict__ xk) {
    float* x = blockIdx.y ? xk : xq;
    const int gt   = blockIdx.x * blockDim.x + threadIdx.x;
    const int gw   = gt >> 5;
    const int lane = gt & 31;
    if (gw >= CB * CS * CH) return;

    const int sPos = (gw / CH) % CS;
    float* p = x + (size_t)gw * CHD;

    const float x1 = p[lane];
    const float x2 = p[lane + 32];

    const float ex = (float)(2 * lane) * (1.0f / 64.0f);
    const float fr = powf(100000.0f, ex);
    const float g  = (float)sPos * (1.0f / fr);
    const float cc = __bfloat162float(__float2bfloat16(cosf(g)));
    const float sn = __bfloat162float(__float2bfloat16(sinf(g)));

    const float y1 = x1 * cc + x2 * sn;
    const float y2 = -x1 * sn + x2 * cc;

    float ss = y1 * y1 + y2 * y2;
#pragma unroll
    for (int o = 16; o > 0; o >>= 1) ss += __shfl_xor_sync(0xffffffffu, ss, o);

    const float rms = sqrtf(ss * (1.0f / 64.0f) + 1e-9f);
    const float ir  = 1.0f / rms;
    p[lane]      = y1 * ir;
    p[lane + 32] = y2 * ir;
}

// ---------------------------------------------------------------------------
// Causal flash attention with TF32 tensor cores (unchanged from R6 best).
// ---------------------------------------------------------------------------
__global__ __launch_bounds__(256, 2) void flash_attn_tc(
    const float* __restrict__ q, const float* __restrict__ k,
    const float* __restrict__ v, float* __restrict__ o) {
    __shared__ float Ks[2][32][68];
    __shared__ float Vs[2][32][68];

    const int t    = threadIdx.x;
    const int lane = t & 31;
    const int warp = t >> 5;
    const int gid  = lane >> 2;
    const int tg   = lane & 3;

    const int q0 = (gridDim.x - 1 - blockIdx.x) * 128;
    const int bh = blockIdx.y;
    const size_t base = ((size_t)(bh >> 4) * CS * CH + (bh & 15)) * CHD;
    const int rs = CH * CHD;

    const int qrow0 = q0 + warp * 16 + gid;
    const int qrow1 = qrow0 + 8;

    const int frr = t >> 3;
    const int fdc = (t & 7) * 8;

    uint32_t qa[8][4];
#pragma unroll
    for (int ks = 0; ks < 8; ++ks) {
        qa[ks][0] = f2tf32(0.125f * q[base + (size_t)qrow0 * rs + ks * 8 + tg]);
        qa[ks][1] = f2tf32(0.125f * q[base + (size_t)qrow1 * rs + ks * 8 + tg]);
        qa[ks][2] = f2tf32(0.125f * q[base + (size_t)qrow0 * rs + ks * 8 + tg + 4]);
        qa[ks][3] = f2tf32(0.125f * q[base + (size_t)qrow1 * rs + ks * 8 + tg + 4]);
    }

    float oa[8][4];
#pragma unroll
    for (int dt = 0; dt < 8; ++dt)
#pragma unroll
        for (int i = 0; i < 4; ++i) oa[dt][i] = 0.f;

    float m0 = -1e30f, m1 = -1e30f, l0 = 0.f, l1 = 0.f;

    {
        const size_t gi = base + (size_t)frr * rs + fdc;
        *(float4*)&Ks[0][frr][fdc]     = *(const float4*)&k[gi];
        *(float4*)&Ks[0][frr][fdc + 4] = *(const float4*)&k[gi + 4];
        *(float4*)&Vs[0][frr][fdc]     = *(const float4*)&v[gi];
        *(float4*)&Vs[0][frr][fdc + 4] = *(const float4*)&v[gi + 4];
    }
    __syncthreads();

    const int nkt = (q0 >> 5) + 4;
    for (int kt = 0; kt < nkt; ++kt) {
        const int stage = kt & 1;
        const bool has_next = (kt + 1 < nkt);

        float4 kr0, kr1, vr0, vr1;
        if (has_next) {
            const size_t gi = base + (size_t)(((kt + 1) << 5) + frr) * rs + fdc;
            kr0 = *(const float4*)&k[gi];
            kr1 = *(const float4*)&k[gi + 4];
            vr0 = *(const float4*)&v[gi];
            vr1 = *(const float4*)&v[gi + 4];
        }

        const int kv0 = kt << 5;

        float sc[4][4];
#pragma unroll
        for (int nt = 0; nt < 4; ++nt)
#pragma unroll
            for (int i = 0; i < 4; ++i) sc[nt][i] = 0.f;

#pragma unroll
        for (int ks = 0; ks < 8; ++ks) {
#pragma unroll
            for (int nt = 0; nt < 4; ++nt) {
                uint32_t b[2];
                b[0] = f2tf32(Ks[stage][nt * 8 + gid][ks * 8 + tg]);
                b[1] = f2tf32(Ks[stage][nt * 8 + gid][ks * 8 + tg + 4]);
                mma_tf32(sc[nt], qa[ks], b);
            }
        }

        const bool needmask = (kv0 + 31 > qrow0);
        if (needmask) {
#pragma unroll
            for (int nt = 0; nt < 4; ++nt) {
                const int c0 = kv0 + nt * 8 + 2 * tg;
                const int c1 = c0 + 1;
                if (c0 > qrow0) sc[nt][0] = -1e9f;
                if (c1 > qrow0) sc[nt][1] = -1e9f;
                if (c0 > qrow1) sc[nt][2] = -1e9f;
                if (c1 > qrow1) sc[nt][3] = -1e9f;
            }
        }

        float tm0 = -1e30f, tm1 = -1e30f;
#pragma unroll
        for (int nt = 0; nt < 4; ++nt) {
            tm0 = fmaxf(tm0, fmaxf(sc[nt][0], sc[nt][1]));
            tm1 = fmaxf(tm1, fmaxf(sc[nt][2], sc[nt][3]));
        }
        tm0 = fmaxf(tm0, __shfl_xor_sync(0xffffffffu, tm0, 1));
        tm0 = fmaxf(tm0, __shfl_xor_sync(0xffffffffu, tm0, 2));
        tm1 = fmaxf(tm1, __shfl_xor_sync(0xffffffffu, tm1, 1));
        tm1 = fmaxf(tm1, __shfl_xor_sync(0xffffffffu, tm1, 2));

        const float m0n = fmaxf(m0, tm0);
        const float m1n = fmaxf(m1, tm1);
        const float a0  = __expf(m0 - m0n);
        const float a1  = __expf(m1 - m1n);

        uint32_t pt[4][4];
        float s0 = 0.f, s1 = 0.f;
#pragma unroll
        for (int nt = 0; nt < 4; ++nt) {
            const float p00 = __expf(sc[nt][0] - m0n);
            const float p01 = __expf(sc[nt][1] - m0n);
            const float p10 = __expf(sc[nt][2] - m1n);
            const float p11 = __expf(sc[nt][3] - m1n);
            s0 += p00 + p01;
            s1 += p10 + p11;
            pt[nt][0] = f2tf32(p00);
            pt[nt][1] = f2tf32(p01);
            pt[nt][2] = f2tf32(p10);
            pt[nt][3] = f2tf32(p11);
        }
        s0 += __shfl_xor_sync(0xffffffffu, s0, 1);
        s0 += __shfl_xor_sync(0xffffffffu, s0, 2);
        s1 += __shfl_xor_sync(0xffffffffu, s1, 1);
        s1 += __shfl_xor_sync(0xffffffffu, s1, 2);

        l0 = l0 * a0 + s0;
        l1 = l1 * a1 + s1;
        m0 = m0n;
        m1 = m1n;

#pragma unroll
        for (int dt = 0; dt < 8; ++dt) {
            oa[dt][0] *= a0;
            oa[dt][1] *= a0;
            oa[dt][2] *= a1;
            oa[dt][3] *= a1;
        }

        const int src0 = (lane & ~3) | (tg >> 1);
        const int src2 = src0 + 2;
        const bool odd = (tg & 1);
#pragma unroll
        for (int ks2 = 0; ks2 < 4; ++ks2) {
            uint32_t a00 = __shfl_sync(0xffffffffu, pt[ks2][0], src0);
            uint32_t a01 = __shfl_sync(0xffffffffu, pt[ks2][1], src0);
            uint32_t a10 = __shfl_sync(0xffffffffu, pt[ks2][2], src0);
            uint32_t a11 = __shfl_sync(0xffffffffu, pt[ks2][3], src0);
            uint32_t b00 = __shfl_sync(0xffffffffu, pt[ks2][0], src2);
            uint32_t b01 = __shfl_sync(0xffffffffu, pt[ks2][1], src2);
            uint32_t b10 = __shfl_sync(0xffffffffu, pt[ks2][2], src2);
            uint32_t b11 = __shfl_sync(0xffffffffu, pt[ks2][3], src2);
            uint32_t pa[4];
            pa[0] = odd ? a01 : a00;
            pa[1] = odd ? a11 : a10;
            pa[2] = odd ? b01 : b00;
            pa[3] = odd ? b11 : b10;
#pragma unroll
            for (int dt = 0; dt < 8; ++dt) {
                uint32_t b[2];
                b[0] = f2tf32(Vs[stage][ks2 * 8 + tg][dt * 8 + gid]);
                b[1] = f2tf32(Vs[stage][ks2 * 8 + tg + 4][dt * 8 + gid]);
                mma_tf32(oa[dt], pa, b);
            }
        }

        if (has_next) {
            const int ns = stage ^ 1;
            *(float4*)&Ks[ns][frr][fdc]     = kr0;
            *(float4*)&Ks[ns][frr][fdc + 4] = kr1;
            *(float4*)&Vs[ns][frr][fdc]     = vr0;
            *(float4*)&Vs[ns][frr][fdc + 4] = vr1;
        }
        __syncthreads();
    }

    const float il0 = 1.0f / l0;
    const float il1 = 1.0f / l1;
#pragma unroll
    for (int dt = 0; dt < 8; ++dt) {
        const int cc = dt * 8 + 2 * tg;
        *(float2*)&o[base + (size_t)qrow0 * rs + cc] =
            make_float2(oa[dt][0] * il0, oa[dt][1] * il0);
        *(float2*)&o[base + (size_t)qrow1 * rs + cc] =
            make_float2(oa[dt][2] * il1, oa[dt][3] * il1);
    }
}

// ---------------------------------------------------------------------------
// Launch
// ---------------------------------------------------------------------------
extern "C" void kernel_launch(void* const* d_in, const int* in_sizes, int n_in,
                              void* d_out, int out_size) {
    (void)in_sizes; (void)n_in; (void)out_size;
    const float* Q  = (const float*)d_in[0];
    const float* K  = (const float*)d_in[1];
    const float* V  = (const float*)d_in[2];
    const float* Wq = (const float*)d_in[4];
    const float* Wk = (const float*)d_in[5];
    const float* Wv = (const float*)d_in[6];
    const float* Wo = (const float*)d_in[7];
    float* out = (float*)d_out;

    float *gq, *gk, *gv, *gvals;
    cudaGetSymbolAddress((void**)&gq, g_q);
    cudaGetSymbolAddress((void**)&gk, g_k);
    cudaGetSymbolAddress((void**)&gv, g_v);
    cudaGetSymbolAddress((void**)&gvals, g_vals);

    cudaFuncSetAttribute(sgemm_tf32_v6,
                         cudaFuncAttributeMaxDynamicSharedMemorySize,
                         GEMM_SMEM6);

    const int M = MT;  // 4096

    // Batched QKV projections
    dim3 ggrid3(CD / BN, M / BM, 3);  // (8, 32, 3)
    sgemm_tf32_v6<<<ggrid3, 256, GEMM_SMEM6>>>(Q, K, V, Wq, Wk, Wv, gq, gk, gv,
                                               M, CD, CD);

    const int nwarps = CB * CS * CH;  // 65536
    dim3 rgrid(nwarps / 8, 2);
    rope_rms_kernel<<<rgrid, 256>>>(gq, gk);

    dim3 agrid(CS / 128, CB * CH);    // (16, 32)
    flash_attn_tc<<<agrid, 256>>>(gq, gk, gv, gvals);

    // Output projection
    dim3 ggrid1(CD / BN, M / BM, 1);
    sgemm_tf32_v6<<<ggrid1, 256, GEMM_SMEM6>>>(gvals, nullptr, nullptr, Wo,
                                               nullptr, nullptr, out, nullptr,
                                               nullptr, M, CD, CD);
}

// round 11
// speedup vs baseline: 1.0289x; 1.0289x over previous
#include <cuda_runtime.h>
#include <cuda_bf16.h>
#include <math.h>
#include <stdint.h>

// Problem constants
constexpr int CB  = 2;
constexpr int CS  = 2048;
constexpr int CD  = 1024;
constexpr int CH  = 16;
constexpr int CHD = 64;
constexpr int MT  = CB * CS;  // 4096

// Scratch (allocation-free rule: static __device__ arrays)
__device__ __align__(256) float g_q[MT * CD];
__device__ __align__(256) float g_k[MT * CD];
__device__ __align__(256) float g_v[MT * CD];
__device__ __align__(256) float g_vals[MT * CD];
__device__ __align__(256) float g_qi[MT * CD];   // tf32 bits of inputs
__device__ __align__(256) float g_ki[MT * CD];
__device__ __align__(256) float g_vi[MT * CD];
__device__ __align__(256) float g_wt[4 * CD * CD];  // tf32 bits of weights

// ---------------------------------------------------------------------------
// TF32 helpers
// ---------------------------------------------------------------------------
__device__ __forceinline__ uint32_t f2tf32(float x) {
    uint32_t u;
    asm("cvt.rna.tf32.f32 %0, %1;" : "=r"(u) : "f"(x));
    return u;
}

__device__ __forceinline__ float f2tf32f(float x) {
    return __uint_as_float(f2tf32(x));
}

__device__ __forceinline__ void mma_tf32(float c[4], const uint32_t a[4],
                                         const uint32_t b[2]) {
    asm volatile(
        "mma.sync.aligned.m16n8k8.row.col.f32.tf32.tf32.f32 "
        "{%0,%1,%2,%3}, {%4,%5,%6,%7}, {%8,%9}, {%0,%1,%2,%3};"
        : "+f"(c[0]), "+f"(c[1]), "+f"(c[2]), "+f"(c[3])
        : "r"(a[0]), "r"(a[1]), "r"(a[2]), "r"(a[3]), "r"(b[0]), "r"(b[1]));
}

__device__ __forceinline__ uint32_t smem_u32(const void* p) {
    uint32_t a;
    asm("{ .reg .u64 t; cvta.to.shared.u64 t, %1; cvt.u32.u64 %0, t; }"
        : "=r"(a) : "l"(p));
    return a;
}

__device__ __forceinline__ void cp16(uint32_t dst, const void* src) {
    asm volatile("cp.async.cg.shared.global [%0], [%1], 16;"
                 :: "r"(dst), "l"(src) : "memory");
}
#define CP_COMMIT() asm volatile("cp.async.commit_group;" ::: "memory")
#define CP_WAIT1()  asm volatile("cp.async.wait_group 1;" ::: "memory")

// ---------------------------------------------------------------------------
// prep: convert Q,K,V inputs and 4 weights to tf32 bits (once per element).
// blockIdx.y: 0..2 activations, 3..6 weights.
// ---------------------------------------------------------------------------
__global__ __launch_bounds__(256) void prep_cvt(
    const float* __restrict__ Q, const float* __restrict__ K,
    const float* __restrict__ V, const float* __restrict__ Wq,
    const float* __restrict__ Wk, const float* __restrict__ Wv,
    const float* __restrict__ Wo, float* __restrict__ qi,
    float* __restrict__ ki, float* __restrict__ vi, float* __restrict__ wt) {
    const int y = blockIdx.y;
    const float* src;
    float* dst;
    int n4;
    if (y < 3) {
        src = (y == 0) ? Q : (y == 1) ? K : V;
        dst = (y == 0) ? qi : (y == 1) ? ki : vi;
        n4 = MT * CD / 4;
    } else {
        const int w = y - 3;
        src = (w == 0) ? Wq : (w == 1) ? Wk : (w == 2) ? Wv : Wo;
        dst = wt + (size_t)w * CD * CD;
        n4 = CD * CD / 4;
    }
    const int i = blockIdx.x * 256 + threadIdx.x;
    if (i >= n4) return;
    float4 v = ((const float4*)src)[i];
    v.x = f2tf32f(v.x);
    v.y = f2tf32f(v.y);
    v.z = f2tf32f(v.z);
    v.w = f2tf32f(v.w);
    ((float4*)dst)[i] = v;
}

// ---------------------------------------------------------------------------
// TF32 tensor-core GEMM v7: v5 pipeline (cp.async 3-stage, BK=32, 128 thr,
// 64x64 warp tiles) but inputs are PRE-CONVERTED tf32 bits -> zero cvts in
// the hot loop. cvtmask bit z => epilogue converts output to tf32 bits.
// ---------------------------------------------------------------------------
constexpr int BM = 128, BN = 128;
constexpr int APAD = 36;
constexpr int BPAD = 136;
constexpr int ABYTES = BM * APAD * 4;
constexpr int BBYTES = 32 * BPAD * 4;
constexpr int STAGEB = ABYTES + BBYTES;
constexpr int GEMM_SMEM7 = 3 * STAGEB;  // 107520

__global__ __launch_bounds__(128) void sgemm_tf32_v7(
    const float* __restrict__ A0, const float* __restrict__ A1,
    const float* __restrict__ A2, const float* __restrict__ W0,
    const float* __restrict__ W1, const float* __restrict__ W2,
    float* __restrict__ C0, float* __restrict__ C1, float* __restrict__ C2,
    int M, int N, int K, int cvtmask) {
    extern __shared__ char smem[];
    const uint32_t sb = smem_u32(smem);

    const int z = blockIdx.z;
    const float* A = (z == 0) ? A0 : (z == 1) ? A1 : A2;
    const float* W = (z == 0) ? W0 : (z == 1) ? W1 : W2;
    float*       C = (z == 0) ? C0 : (z == 1) ? C1 : C2;
    const bool docvt = (cvtmask >> z) & 1;

    const int t    = threadIdx.x;
    const int lane = t & 31;
    const int warp = t >> 5;
    const int wm   = warp & 1;
    const int wn   = warp >> 1;
    const int gid  = lane >> 2;
    const int tg   = lane & 3;

    const int m0b = blockIdx.y * BM;
    const int n0b = blockIdx.x * BN;

    const int NC = K / 32;

    float c[4][8][4];
#pragma unroll
    for (int mt = 0; mt < 4; ++mt)
#pragma unroll
        for (int nt = 0; nt < 8; ++nt)
#pragma unroll
            for (int i = 0; i < 4; ++i) c[mt][nt][i] = 0.f;

    auto issue = [&](int ck, int s) {
        const int kn = ck * 32;
        const uint32_t abase = sb + s * STAGEB;
        const uint32_t bbase = abase + ABYTES;
#pragma unroll
        for (int i = 0; i < 8; ++i) {
            const int ci = t + i * 128;
            const int ar = ci >> 3, as = ci & 7;
            cp16(abase + (ar * APAD + as * 4) * 4,
                 &A[(size_t)(m0b + ar) * K + kn + as * 4]);
            const int br = ci >> 5, bs = ci & 31;
            cp16(bbase + (br * BPAD + bs * 4) * 4,
                 &W[(size_t)(kn + br) * N + n0b + bs * 4]);
        }
        CP_COMMIT();
    };

    issue(0, 0);
    issue(1, 1);

    for (int ck = 0; ck < NC; ++ck) {
        CP_WAIT1();
        __syncthreads();
        if (ck + 2 < NC) issue(ck + 2, (ck + 2) % 3);

        const int s = ck % 3;
        const uint32_t* As = (const uint32_t*)(smem + s * STAGEB);
        const uint32_t* Bs = (const uint32_t*)(smem + s * STAGEB + ABYTES);

#pragma unroll
        for (int kk = 0; kk < 32; kk += 8) {
            uint32_t af[4][4], bf[8][2];
#pragma unroll
            for (int mt = 0; mt < 4; ++mt) {
                const int mm = wm * 64 + mt * 16 + gid;
                af[mt][0] = As[mm * APAD + kk + tg];
                af[mt][1] = As[(mm + 8) * APAD + kk + tg];
                af[mt][2] = As[mm * APAD + kk + tg + 4];
                af[mt][3] = As[(mm + 8) * APAD + kk + tg + 4];
            }
#pragma unroll
            for (int nt = 0; nt < 8; ++nt) {
                const int nn = wn * 64 + nt * 8 + gid;
                bf[nt][0] = Bs[(kk + tg) * BPAD + nn];
                bf[nt][1] = Bs[(kk + tg + 4) * BPAD + nn];
            }
#pragma unroll
            for (int mt = 0; mt < 4; ++mt)
#pragma unroll
                for (int nt = 0; nt < 8; ++nt) mma_tf32(c[mt][nt], af[mt], bf[nt]);
        }
    }

    // epilogue (optionally converting to tf32 bits for downstream consumers)
#pragma unroll
    for (int mt = 0; mt < 4; ++mt) {
        const int r0 = m0b + wm * 64 + mt * 16 + gid;
#pragma unroll
        for (int nt = 0; nt < 8; ++nt) {
            const int cc = n0b + wn * 64 + nt * 8 + tg * 2;
            float v0 = c[mt][nt][0], v1 = c[mt][nt][1];
            float v2 = c[mt][nt][2], v3 = c[mt][nt][3];
            if (docvt) {
                v0 = f2tf32f(v0);
                v1 = f2tf32f(v1);
                v2 = f2tf32f(v2);
                v3 = f2tf32f(v3);
            }
            *(float2*)&C[(size_t)r0 * N + cc]       = make_float2(v0, v1);
            *(float2*)&C[(size_t)(r0 + 8) * N + cc] = make_float2(v2, v3);
        }
    }
}

// ---------------------------------------------------------------------------
// RoPE (bf16 cos/sin tables) + RMSNorm, in place. blockIdx.y: 0=q, 1=k.
// For k (y==1) the output is stored as tf32 bits (consumed raw by attention).
// ---------------------------------------------------------------------------
__global__ __launch_bounds__(256) void rope_rms_kernel(float* __restrict__ xq,
                                                       float* __restrict__ xk) {
    const bool isk = blockIdx.y;
    float* x = isk ? xk : xq;
    const int gt   = blockIdx.x * blockDim.x + threadIdx.x;
    const int gw   = gt >> 5;
    const int lane = gt & 31;
    if (gw >= CB * CS * CH) return;

    const int sPos = (gw / CH) % CS;
    float* p = x + (size_t)gw * CHD;

    const float x1 = p[lane];
    const float x2 = p[lane + 32];

    const float ex = (float)(2 * lane) * (1.0f / 64.0f);
    const float fr = powf(100000.0f, ex);
    const float g  = (float)sPos * (1.0f / fr);
    const float cc = __bfloat162float(__float2bfloat16(cosf(g)));
    const float sn = __bfloat162float(__float2bfloat16(sinf(g)));

    const float y1 = x1 * cc + x2 * sn;
    const float y2 = -x1 * sn + x2 * cc;

    float ss = y1 * y1 + y2 * y2;
#pragma unroll
    for (int o = 16; o > 0; o >>= 1) ss += __shfl_xor_sync(0xffffffffu, ss, o);

    const float rms = sqrtf(ss * (1.0f / 64.0f) + 1e-9f);
    const float ir  = 1.0f / rms;
    float o1 = y1 * ir, o2 = y2 * ir;
    if (isk) {
        o1 = f2tf32f(o1);
        o2 = f2tf32f(o2);
    }
    p[lane]      = o1;
    p[lane + 32] = o2;
}

// ---------------------------------------------------------------------------
// Causal flash attention, TF32 tensor cores. K and V arrive as tf32 bits in
// gmem -> fragment loads are plain LDS (no cvt). Output written as tf32 bits
// (consumed raw by the Wo GEMM).
// ---------------------------------------------------------------------------
__global__ __launch_bounds__(256, 2) void flash_attn_tc(
    const float* __restrict__ q, const float* __restrict__ k,
    const float* __restrict__ v, float* __restrict__ o) {
    __shared__ float Ks[2][32][68];
    __shared__ float Vs[2][32][68];

    const int t    = threadIdx.x;
    const int lane = t & 31;
    const int warp = t >> 5;
    const int gid  = lane >> 2;
    const int tg   = lane & 3;

    const int q0 = (gridDim.x - 1 - blockIdx.x) * 128;
    const int bh = blockIdx.y;
    const size_t base = ((size_t)(bh >> 4) * CS * CH + (bh & 15)) * CHD;
    const int rs = CH * CHD;

    const int qrow0 = q0 + warp * 16 + gid;
    const int qrow1 = qrow0 + 8;

    const int frr = t >> 3;
    const int fdc = (t & 7) * 8;

    uint32_t qa[8][4];
#pragma unroll
    for (int ks = 0; ks < 8; ++ks) {
        qa[ks][0] = f2tf32(0.125f * q[base + (size_t)qrow0 * rs + ks * 8 + tg]);
        qa[ks][1] = f2tf32(0.125f * q[base + (size_t)qrow1 * rs + ks * 8 + tg]);
        qa[ks][2] = f2tf32(0.125f * q[base + (size_t)qrow0 * rs + ks * 8 + tg + 4]);
        qa[ks][3] = f2tf32(0.125f * q[base + (size_t)qrow1 * rs + ks * 8 + tg + 4]);
    }

    float oa[8][4];
#pragma unroll
    for (int dt = 0; dt < 8; ++dt)
#pragma unroll
        for (int i = 0; i < 4; ++i) oa[dt][i] = 0.f;

    float m0 = -1e30f, m1 = -1e30f, l0 = 0.f, l1 = 0.f;

    {
        const size_t gi = base + (size_t)frr * rs + fdc;
        *(float4*)&Ks[0][frr][fdc]     = *(const float4*)&k[gi];
        *(float4*)&Ks[0][frr][fdc + 4] = *(const float4*)&k[gi + 4];
        *(float4*)&Vs[0][frr][fdc]     = *(const float4*)&v[gi];
        *(float4*)&Vs[0][frr][fdc + 4] = *(const float4*)&v[gi + 4];
    }
    __syncthreads();

    const int nkt = (q0 >> 5) + 4;
    for (int kt = 0; kt < nkt; ++kt) {
        const int stage = kt & 1;
        const bool has_next = (kt + 1 < nkt);

        float4 kr0, kr1, vr0, vr1;
        if (has_next) {
            const size_t gi = base + (size_t)(((kt + 1) << 5) + frr) * rs + fdc;
            kr0 = *(const float4*)&k[gi];
            kr1 = *(const float4*)&k[gi + 4];
            vr0 = *(const float4*)&v[gi];
            vr1 = *(const float4*)&v[gi + 4];
        }

        const int kv0 = kt << 5;

        float sc[4][4];
#pragma unroll
        for (int nt = 0; nt < 4; ++nt)
#pragma unroll
            for (int i = 0; i < 4; ++i) sc[nt][i] = 0.f;

#pragma unroll
        for (int ks = 0; ks < 8; ++ks) {
#pragma unroll
            for (int nt = 0; nt < 4; ++nt) {
                uint32_t b[2];
                b[0] = __float_as_uint(Ks[stage][nt * 8 + gid][ks * 8 + tg]);
                b[1] = __float_as_uint(Ks[stage][nt * 8 + gid][ks * 8 + tg + 4]);
                mma_tf32(sc[nt], qa[ks], b);
            }
        }

        const bool needmask = (kv0 + 31 > qrow0);
        if (needmask) {
#pragma unroll
            for (int nt = 0; nt < 4; ++nt) {
                const int c0 = kv0 + nt * 8 + 2 * tg;
                const int c1 = c0 + 1;
                if (c0 > qrow0) sc[nt][0] = -1e9f;
                if (c1 > qrow0) sc[nt][1] = -1e9f;
                if (c0 > qrow1) sc[nt][2] = -1e9f;
                if (c1 > qrow1) sc[nt][3] = -1e9f;
            }
        }

        float tm0 = -1e30f, tm1 = -1e30f;
#pragma unroll
        for (int nt = 0; nt < 4; ++nt) {
            tm0 = fmaxf(tm0, fmaxf(sc[nt][0], sc[nt][1]));
            tm1 = fmaxf(tm1, fmaxf(sc[nt][2], sc[nt][3]));
        }
        tm0 = fmaxf(tm0, __shfl_xor_sync(0xffffffffu, tm0, 1));
        tm0 = fmaxf(tm0, __shfl_xor_sync(0xffffffffu, tm0, 2));
        tm1 = fmaxf(tm1, __shfl_xor_sync(0xffffffffu, tm1, 1));
        tm1 = fmaxf(tm1, __shfl_xor_sync(0xffffffffu, tm1, 2));

        const float m0n = fmaxf(m0, tm0);
        const float m1n = fmaxf(m1, tm1);
        const float a0  = __expf(m0 - m0n);
        const float a1  = __expf(m1 - m1n);

        uint32_t pt[4][4];
        float s0 = 0.f, s1 = 0.f;
#pragma unroll
        for (int nt = 0; nt < 4; ++nt) {
            const float p00 = __expf(sc[nt][0] - m0n);
            const float p01 = __expf(sc[nt][1] - m0n);
            const float p10 = __expf(sc[nt][2] - m1n);
            const float p11 = __expf(sc[nt][3] - m1n);
            s0 += p00 + p01;
            s1 += p10 + p11;
            pt[nt][0] = f2tf32(p00);
            pt[nt][1] = f2tf32(p01);
            pt[nt][2] = f2tf32(p10);
            pt[nt][3] = f2tf32(p11);
        }
        s0 += __shfl_xor_sync(0xffffffffu, s0, 1);
        s0 += __shfl_xor_sync(0xffffffffu, s0, 2);
        s1 += __shfl_xor_sync(0xffffffffu, s1, 1);
        s1 += __shfl_xor_sync(0xffffffffu, s1, 2);

        l0 = l0 * a0 + s0;
        l1 = l1 * a1 + s1;
        m0 = m0n;
        m1 = m1n;

#pragma unroll
        for (int dt = 0; dt < 8; ++dt) {
            oa[dt][0] *= a0;
            oa[dt][1] *= a0;
            oa[dt][2] *= a1;
            oa[dt][3] *= a1;
        }

        const int src0 = (lane & ~3) | (tg >> 1);
        const int src2 = src0 + 2;
        const bool odd = (tg & 1);
#pragma unroll
        for (int ks2 = 0; ks2 < 4; ++ks2) {
            uint32_t a00 = __shfl_sync(0xffffffffu, pt[ks2][0], src0);
            uint32_t a01 = __shfl_sync(0xffffffffu, pt[ks2][1], src0);
            uint32_t a10 = __shfl_sync(0xffffffffu, pt[ks2][2], src0);
            uint32_t a11 = __shfl_sync(0xffffffffu, pt[ks2][3], src0);
            uint32_t b00 = __shfl_sync(0xffffffffu, pt[ks2][0], src2);
            uint32_t b01 = __shfl_sync(0xffffffffu, pt[ks2][1], src2);
            uint32_t b10 = __shfl_sync(0xffffffffu, pt[ks2][2], src2);
            uint32_t b11 = __shfl_sync(0xffffffffu, pt[ks2][3], src2);
            uint32_t pa[4];
            pa[0] = odd ? a01 : a00;
            pa[1] = odd ? a11 : a10;
            pa[2] = odd ? b01 : b00;
            pa[3] = odd ? b11 : b10;
#pragma unroll
            for (int dt = 0; dt < 8; ++dt) {
                uint32_t b[2];
                b[0] = __float_as_uint(Vs[stage][ks2 * 8 + tg][dt * 8 + gid]);
                b[1] = __float_as_uint(Vs[stage][ks2 * 8 + tg + 4][dt * 8 + gid]);
                mma_tf32(oa[dt], pa, b);
            }
        }

        if (has_next) {
            const int ns = stage ^ 1;
            *(float4*)&Ks[ns][frr][fdc]     = kr0;
            *(float4*)&Ks[ns][frr][fdc + 4] = kr1;
            *(float4*)&Vs[ns][frr][fdc]     = vr0;
            *(float4*)&Vs[ns][frr][fdc + 4] = vr1;
        }
        __syncthreads();
    }

    const float il0 = 1.0f / l0;
    const float il1 = 1.0f / l1;
#pragma unroll
    for (int dt = 0; dt < 8; ++dt) {
        const int cc = dt * 8 + 2 * tg;
        *(float2*)&o[base + (size_t)qrow0 * rs + cc] =
            make_float2(f2tf32f(oa[dt][0] * il0), f2tf32f(oa[dt][1] * il0));
        *(float2*)&o[base + (size_t)qrow1 * rs + cc] =
            make_float2(f2tf32f(oa[dt][2] * il1), f2tf32f(oa[dt][3] * il1));
    }
}

// ---------------------------------------------------------------------------
// Launch
// ---------------------------------------------------------------------------
extern "C" void kernel_launch(void* const* d_in, const int* in_sizes, int n_in,
                              void* d_out, int out_size) {
    (void)in_sizes; (void)n_in; (void)out_size;
    const float* Q  = (const float*)d_in[0];
    const float* K  = (const float*)d_in[1];
    const float* V  = (const float*)d_in[2];
    const float* Wq = (const float*)d_in[4];
    const float* Wk = (const float*)d_in[5];
    const float* Wv = (const float*)d_in[6];
    const float* Wo = (const float*)d_in[7];
    float* out = (float*)d_out;

    float *gq, *gk, *gv, *gvals, *qi, *ki, *vi, *wt;
    cudaGetSymbolAddress((void**)&gq, g_q);
    cudaGetSymbolAddress((void**)&gk, g_k);
    cudaGetSymbolAddress((void**)&gv, g_v);
    cudaGetSymbolAddress((void**)&gvals, g_vals);
    cudaGetSymbolAddress((void**)&qi, g_qi);
    cudaGetSymbolAddress((void**)&ki, g_ki);
    cudaGetSymbolAddress((void**)&vi, g_vi);
    cudaGetSymbolAddress((void**)&wt, g_wt);

    cudaFuncSetAttribute(sgemm_tf32_v7,
                         cudaFuncAttributeMaxDynamicSharedMemorySize,
                         GEMM_SMEM7);

    const int M = MT;  // 4096

    // 0) pre-convert inputs + weights to tf32 bits
    dim3 pgrid(MT * CD / 4 / 256, 7);  // (4096, 7)
    prep_cvt<<<pgrid, 256>>>(Q, K, V, Wq, Wk, Wv, Wo, qi, ki, vi, wt);

    // 1) QKV projections (V output converted to tf32 bits in epilogue)
    dim3 ggrid3(CD / BN, M / BM, 3);  // (8, 32, 3)
    sgemm_tf32_v7<<<ggrid3, 128, GEMM_SMEM7>>>(
        qi, ki, vi, wt, wt + CD * CD, wt + 2 * CD * CD, gq, gk, gv, M, CD, CD,
        0b100);

    // 2) rope+rms (k output stored as tf32 bits)
    const int nwarps = CB * CS * CH;  // 65536
    dim3 rgrid(nwarps / 8, 2);
    rope_rms_kernel<<<rgrid, 256>>>(gq, gk);

    // 3) attention (writes tf32 bits)
    dim3 agrid(CS / 128, CB * CH);    // (16, 32)
    flash_attn_tc<<<agrid, 256>>>(gq, gk, gv, gvals);

    // 4) output projection (fp32 out)
    dim3 ggrid1(CD / BN, M / BM, 1);
    sgemm_tf32_v7<<<ggrid1, 128, GEMM_SMEM7>>>(
        gvals, nullptr, nullptr, wt + 3 * CD * CD, nullptr, nullptr, out,
        nullptr, nullptr, M, CD, CD, 0);
}

// round 12
// speedup vs baseline: 1.3786x; 1.3399x over previous
#include <cuda_runtime.h>
#include <cuda_bf16.h>
#include <cuda_fp16.h>
#include <math.h>
#include <stdint.h>

// Problem constants
constexpr int CB  = 2;
constexpr int CS  = 2048;
constexpr int CD  = 1024;
constexpr int CH  = 16;
constexpr int CHD = 64;
constexpr int MT  = CB * CS;  // 4096

// Scratch (allocation-free rule: static __device__ arrays)
__device__ __align__(256) float g_q[MT * CD];
__device__ __align__(256) float g_k[MT * CD];
__device__ __align__(256) float g_v[MT * CD];
__device__ __align__(256) float g_vals[MT * CD];
__device__ __align__(256) float g_qi[MT * CD];   // tf32 bits of inputs
__device__ __align__(256) float g_ki[MT * CD];
__device__ __align__(256) float g_vi[MT * CD];
__device__ __align__(256) float g_wt[4 * CD * CD];  // tf32 bits of weights
__device__ __align__(256) __half g_kh[MT * CD];     // fp16 K after rope+rms

// ---------------------------------------------------------------------------
// Helpers
// ---------------------------------------------------------------------------
__device__ __forceinline__ uint32_t f2tf32(float x) {
    uint32_t u;
    asm("cvt.rna.tf32.f32 %0, %1;" : "=r"(u) : "f"(x));
    return u;
}

__device__ __forceinline__ float f2tf32f(float x) {
    return __uint_as_float(f2tf32(x));
}

__device__ __forceinline__ uint32_t packh2(float lo, float hi) {
    __half2 h = __floats2half2_rn(lo, hi);
    return *(uint32_t*)&h;
}

__device__ __forceinline__ void mma_tf32(float c[4], const uint32_t a[4],
                                         const uint32_t b[2]) {
    asm volatile(
        "mma.sync.aligned.m16n8k8.row.col.f32.tf32.tf32.f32 "
        "{%0,%1,%2,%3}, {%4,%5,%6,%7}, {%8,%9}, {%0,%1,%2,%3};"
        : "+f"(c[0]), "+f"(c[1]), "+f"(c[2]), "+f"(c[3])
        : "r"(a[0]), "r"(a[1]), "r"(a[2]), "r"(a[3]), "r"(b[0]), "r"(b[1]));
}

__device__ __forceinline__ void mma_f16(float c[4], const uint32_t a[4],
                                        const uint32_t b[2]) {
    asm volatile(
        "mma.sync.aligned.m16n8k16.row.col.f32.f16.f16.f32 "
        "{%0,%1,%2,%3}, {%4,%5,%6,%7}, {%8,%9}, {%0,%1,%2,%3};"
        : "+f"(c[0]), "+f"(c[1]), "+f"(c[2]), "+f"(c[3])
        : "r"(a[0]), "r"(a[1]), "r"(a[2]), "r"(a[3]), "r"(b[0]), "r"(b[1]));
}

__device__ __forceinline__ uint32_t smem_u32(const void* p) {
    uint32_t a;
    asm("{ .reg .u64 t; cvta.to.shared.u64 t, %1; cvt.u32.u64 %0, t; }"
        : "=r"(a) : "l"(p));
    return a;
}

__device__ __forceinline__ void cp16(uint32_t dst, const void* src) {
    asm volatile("cp.async.cg.shared.global [%0], [%1], 16;"
                 :: "r"(dst), "l"(src) : "memory");
}
#define CP_COMMIT() asm volatile("cp.async.commit_group;" ::: "memory")
#define CP_WAIT1()  asm volatile("cp.async.wait_group 1;" ::: "memory")

// ---------------------------------------------------------------------------
// prep: convert Q,K,V inputs and 4 weights to tf32 bits (once per element).
// ---------------------------------------------------------------------------
__global__ __launch_bounds__(256) void prep_cvt(
    const float* __restrict__ Q, const float* __restrict__ K,
    const float* __restrict__ V, const float* __restrict__ Wq,
    const float* __restrict__ Wk, const float* __restrict__ Wv,
    const float* __restrict__ Wo, float* __restrict__ qi,
    float* __restrict__ ki, float* __restrict__ vi, float* __restrict__ wt) {
    const int y = blockIdx.y;
    const float* src;
    float* dst;
    int n4;
    if (y < 3) {
        src = (y == 0) ? Q : (y == 1) ? K : V;
        dst = (y == 0) ? qi : (y == 1) ? ki : vi;
        n4 = MT * CD / 4;
    } else {
        const int w = y - 3;
        src = (w == 0) ? Wq : (w == 1) ? Wk : (w == 2) ? Wv : Wo;
        dst = wt + (size_t)w * CD * CD;
        n4 = CD * CD / 4;
    }
    const int i = blockIdx.x * 256 + threadIdx.x;
    if (i >= n4) return;
    float4 v = ((const float4*)src)[i];
    v.x = f2tf32f(v.x);
    v.y = f2tf32f(v.y);
    v.z = f2tf32f(v.z);
    v.w = f2tf32f(v.w);
    ((float4*)dst)[i] = v;
}

// ---------------------------------------------------------------------------
// TF32 tensor-core GEMM v7 (pre-converted tf32-bit inputs, zero hot-loop cvt).
// ---------------------------------------------------------------------------
constexpr int BM = 128, BN = 128;
constexpr int APAD = 36;
constexpr int BPAD = 136;
constexpr int ABYTES = BM * APAD * 4;
constexpr int BBYTES = 32 * BPAD * 4;
constexpr int STAGEB = ABYTES + BBYTES;
constexpr int GEMM_SMEM7 = 3 * STAGEB;  // 107520

__global__ __launch_bounds__(128) void sgemm_tf32_v7(
    const float* __restrict__ A0, const float* __restrict__ A1,
    const float* __restrict__ A2, const float* __restrict__ W0,
    const float* __restrict__ W1, const float* __restrict__ W2,
    float* __restrict__ C0, float* __restrict__ C1, float* __restrict__ C2,
    int M, int N, int K, int cvtmask) {
    extern __shared__ char smem[];
    const uint32_t sb = smem_u32(smem);

    const int z = blockIdx.z;
    const float* A = (z == 0) ? A0 : (z == 1) ? A1 : A2;
    const float* W = (z == 0) ? W0 : (z == 1) ? W1 : W2;
    float*       C = (z == 0) ? C0 : (z == 1) ? C1 : C2;
    const bool docvt = (cvtmask >> z) & 1;

    const int t    = threadIdx.x;
    const int lane = t & 31;
    const int warp = t >> 5;
    const int wm   = warp & 1;
    const int wn   = warp >> 1;
    const int gid  = lane >> 2;
    const int tg   = lane & 3;

    const int m0b = blockIdx.y * BM;
    const int n0b = blockIdx.x * BN;

    const int NC = K / 32;

    float c[4][8][4];
#pragma unroll
    for (int mt = 0; mt < 4; ++mt)
#pragma unroll
        for (int nt = 0; nt < 8; ++nt)
#pragma unroll
            for (int i = 0; i < 4; ++i) c[mt][nt][i] = 0.f;

    auto issue = [&](int ck, int s) {
        const int kn = ck * 32;
        const uint32_t abase = sb + s * STAGEB;
        const uint32_t bbase = abase + ABYTES;
#pragma unroll
        for (int i = 0; i < 8; ++i) {
            const int ci = t + i * 128;
            const int ar = ci >> 3, as = ci & 7;
            cp16(abase + (ar * APAD + as * 4) * 4,
                 &A[(size_t)(m0b + ar) * K + kn + as * 4]);
            const int br = ci >> 5, bs = ci & 31;
            cp16(bbase + (br * BPAD + bs * 4) * 4,
                 &W[(size_t)(kn + br) * N + n0b + bs * 4]);
        }
        CP_COMMIT();
    };

    issue(0, 0);
    issue(1, 1);

    for (int ck = 0; ck < NC; ++ck) {
        CP_WAIT1();
        __syncthreads();
        if (ck + 2 < NC) issue(ck + 2, (ck + 2) % 3);

        const int s = ck % 3;
        const uint32_t* As = (const uint32_t*)(smem + s * STAGEB);
        const uint32_t* Bs = (const uint32_t*)(smem + s * STAGEB + ABYTES);

#pragma unroll
        for (int kk = 0; kk < 32; kk += 8) {
            uint32_t af[4][4], bf[8][2];
#pragma unroll
            for (int mt = 0; mt < 4; ++mt) {
                const int mm = wm * 64 + mt * 16 + gid;
                af[mt][0] = As[mm * APAD + kk + tg];
                af[mt][1] = As[(mm + 8) * APAD + kk + tg];
                af[mt][2] = As[mm * APAD + kk + tg + 4];
                af[mt][3] = As[(mm + 8) * APAD + kk + tg + 4];
            }
#pragma unroll
            for (int nt = 0; nt < 8; ++nt) {
                const int nn = wn * 64 + nt * 8 + gid;
                bf[nt][0] = Bs[(kk + tg) * BPAD + nn];
                bf[nt][1] = Bs[(kk + tg + 4) * BPAD + nn];
            }
#pragma unroll
            for (int mt = 0; mt < 4; ++mt)
#pragma unroll
                for (int nt = 0; nt < 8; ++nt) mma_tf32(c[mt][nt], af[mt], bf[nt]);
        }
    }

#pragma unroll
    for (int mt = 0; mt < 4; ++mt) {
        const int r0 = m0b + wm * 64 + mt * 16 + gid;
#pragma unroll
        for (int nt = 0; nt < 8; ++nt) {
            const int cc = n0b + wn * 64 + nt * 8 + tg * 2;
            float v0 = c[mt][nt][0], v1 = c[mt][nt][1];
            float v2 = c[mt][nt][2], v3 = c[mt][nt][3];
            if (docvt) {
                v0 = f2tf32f(v0);
                v1 = f2tf32f(v1);
                v2 = f2tf32f(v2);
                v3 = f2tf32f(v3);
            }
            *(float2*)&C[(size_t)r0 * N + cc]       = make_float2(v0, v1);
            *(float2*)&C[(size_t)(r0 + 8) * N + cc] = make_float2(v2, v3);
        }
    }
}

// ---------------------------------------------------------------------------
// RoPE (bf16 cos/sin tables) + RMSNorm. blockIdx.y: 0=q (in place fp32),
// 1=k (writes fp16 to kh buffer for the fp16 attention).
// ---------------------------------------------------------------------------
__global__ __launch_bounds__(256) void rope_rms_kernel(float* __restrict__ xq,
                                                       float* __restrict__ xk,
                                                       __half* __restrict__ kh) {
    const bool isk = blockIdx.y;
    float* x = isk ? xk : xq;
    const int gt   = blockIdx.x * blockDim.x + threadIdx.x;
    const int gw   = gt >> 5;
    const int lane = gt & 31;
    if (gw >= CB * CS * CH) return;

    const int sPos = (gw / CH) % CS;
    float* p = x + (size_t)gw * CHD;

    const float x1 = p[lane];
    const float x2 = p[lane + 32];

    const float ex = (float)(2 * lane) * (1.0f / 64.0f);
    const float fr = powf(100000.0f, ex);
    const float g  = (float)sPos * (1.0f / fr);
    const float cc = __bfloat162float(__float2bfloat16(cosf(g)));
    const float sn = __bfloat162float(__float2bfloat16(sinf(g)));

    const float y1 = x1 * cc + x2 * sn;
    const float y2 = -x1 * sn + x2 * cc;

    float ss = y1 * y1 + y2 * y2;
#pragma unroll
    for (int o = 16; o > 0; o >>= 1) ss += __shfl_xor_sync(0xffffffffu, ss, o);

    const float rms = sqrtf(ss * (1.0f / 64.0f) + 1e-9f);
    const float ir  = 1.0f / rms;
    const float o1 = y1 * ir, o2 = y2 * ir;
    if (isk) {
        __half* ph = kh + (size_t)gw * CHD;
        ph[lane]      = __float2half_rn(o1);
        ph[lane + 32] = __float2half_rn(o2);
    } else {
        p[lane]      = o1;
        p[lane + 32] = o2;
    }
}

// ---------------------------------------------------------------------------
// Causal flash attention with fp16 m16n8k16 tensor cores (fp32 accumulate).
// 128 q-rows per CTA (8 warps), KV tiles of 32, double-buffered smem.
// K arrives fp16 (from rope); V converted fp32->fp16 at fill, stored
// kv-pair-interleaved so PV b-fragments are single LDS.32. The S c-fragment
// packs directly into the PV a-fragment (fp16 FA identity): zero shuffles.
// Output written as tf32 bits for the Wo GEMM.
// ---------------------------------------------------------------------------
__global__ __launch_bounds__(256, 2) void flash_attn_f16(
    const float* __restrict__ q, const __half* __restrict__ kh,
    const float* __restrict__ v, float* __restrict__ o) {
    __shared__ uint32_t Kw[2][32][36];  // f16x2 words, [kv][d-pair], pad 36
    __shared__ uint32_t Vw[2][16][72];  // f16x2 (V[2r][d],V[2r+1][d]), pad 72

    const int t    = threadIdx.x;
    const int lane = t & 31;
    const int warp = t >> 5;
    const int gid  = lane >> 2;  // 0..7
    const int tg   = lane & 3;   // 0..3

    const int q0 = (gridDim.x - 1 - blockIdx.x) * 128;
    const int bh = blockIdx.y;
    const size_t base = ((size_t)(bh >> 4) * CS * CH + (bh & 15)) * CHD;
    const int rs = CH * CHD;  // 1024

    const int qrow0 = q0 + warp * 16 + gid;
    const int qrow1 = qrow0 + 8;

    // fill mappings
    const int kr_ = t >> 3;        // K row 0..31
    const int kw_ = (t & 7) * 4;   // K word seg (4 words = 8 halves)
    const int vr_ = t >> 4;        // V pair-row 0..15
    const int vw_ = (t & 15) * 4;  // V d-col seg (4 words)

    // Q a-fragments (fp16, 0.125 scale folded — exact power of two)
    uint32_t qa[4][4];
#pragma unroll
    for (int ks = 0; ks < 4; ++ks) {
        const float2 x00 = *(const float2*)&q[base + (size_t)qrow0 * rs + ks * 16 + 2 * tg];
        const float2 x01 = *(const float2*)&q[base + (size_t)qrow0 * rs + ks * 16 + 8 + 2 * tg];
        const float2 x10 = *(const float2*)&q[base + (size_t)qrow1 * rs + ks * 16 + 2 * tg];
        const float2 x11 = *(const float2*)&q[base + (size_t)qrow1 * rs + ks * 16 + 8 + 2 * tg];
        qa[ks][0] = packh2(0.125f * x00.x, 0.125f * x00.y);
        qa[ks][1] = packh2(0.125f * x10.x, 0.125f * x10.y);
        qa[ks][2] = packh2(0.125f * x01.x, 0.125f * x01.y);
        qa[ks][3] = packh2(0.125f * x11.x, 0.125f * x11.y);
    }

    float oa[8][4];
#pragma unroll
    for (int dt = 0; dt < 8; ++dt)
#pragma unroll
        for (int i = 0; i < 4; ++i) oa[dt][i] = 0.f;

    float m0 = -1e30f, m1 = -1e30f, l0 = 0.f, l1 = 0.f;

    // prologue: fill stage 0 with KV tile 0
    {
        *(int4*)&Kw[0][kr_][kw_] =
            *(const int4*)&kh[base + (size_t)kr_ * rs + kw_ * 2];
        const float4 va = *(const float4*)&v[base + (size_t)(2 * vr_) * rs + vw_];
        const float4 vb = *(const float4*)&v[base + (size_t)(2 * vr_ + 1) * rs + vw_];
        uint32_t w[4];
        w[0] = packh2(va.x, vb.x);
        w[1] = packh2(va.y, vb.y);
        w[2] = packh2(va.z, vb.z);
        w[3] = packh2(va.w, vb.w);
        *(int4*)&Vw[0][vr_][vw_] = *(int4*)w;
    }
    __syncthreads();

    const int nkt = (q0 >> 5) + 4;
    for (int kt = 0; kt < nkt; ++kt) {
        const int stage = kt & 1;
        const bool has_next = (kt + 1 < nkt);

        // prefetch next KV tile into registers
        int4 kf;
        float4 va, vb;
        if (has_next) {
            const int kvn = (kt + 1) << 5;
            kf = *(const int4*)&kh[base + (size_t)(kvn + kr_) * rs + kw_ * 2];
            va = *(const float4*)&v[base + (size_t)(kvn + 2 * vr_) * rs + vw_];
            vb = *(const float4*)&v[base + (size_t)(kvn + 2 * vr_ + 1) * rs + vw_];
        }

        const int kv0 = kt << 5;

        // ---- scores: S = (Q/8) K^T via m16n8k16 fp16 ----
        float sc[4][4];
#pragma unroll
        for (int nt = 0; nt < 4; ++nt)
#pragma unroll
            for (int i = 0; i < 4; ++i) sc[nt][i] = 0.f;

#pragma unroll
        for (int ks = 0; ks < 4; ++ks) {
#pragma unroll
            for (int nt = 0; nt < 4; ++nt) {
                uint32_t b[2];
                b[0] = Kw[stage][nt * 8 + gid][ks * 8 + tg];
                b[1] = Kw[stage][nt * 8 + gid][ks * 8 + tg + 4];
                mma_f16(sc[nt], qa[ks], b);
            }
        }

        // ---- causal mask ----
        const bool needmask = (kv0 + 31 > qrow0);
        if (needmask) {
#pragma unroll
            for (int nt = 0; nt < 4; ++nt) {
                const int c0 = kv0 + nt * 8 + 2 * tg;
                const int c1 = c0 + 1;
                if (c0 > qrow0) sc[nt][0] = -1e9f;
                if (c1 > qrow0) sc[nt][1] = -1e9f;
                if (c0 > qrow1) sc[nt][2] = -1e9f;
                if (c1 > qrow1) sc[nt][3] = -1e9f;
            }
        }

        // ---- online softmax (2 rows per thread, quad reductions) ----
        float tm0 = -1e30f, tm1 = -1e30f;
#pragma unroll
        for (int nt = 0; nt < 4; ++nt) {
            tm0 = fmaxf(tm0, fmaxf(sc[nt][0], sc[nt][1]));
            tm1 = fmaxf(tm1, fmaxf(sc[nt][2], sc[nt][3]));
        }
        tm0 = fmaxf(tm0, __shfl_xor_sync(0xffffffffu, tm0, 1));
        tm0 = fmaxf(tm0, __shfl_xor_sync(0xffffffffu, tm0, 2));
        tm1 = fmaxf(tm1, __shfl_xor_sync(0xffffffffu, tm1, 1));
        tm1 = fmaxf(tm1, __shfl_xor_sync(0xffffffffu, tm1, 2));

        const float m0n = fmaxf(m0, tm0);
        const float m1n = fmaxf(m1, tm1);
        const float a0  = __expf(m0 - m0n);
        const float a1  = __expf(m1 - m1n);

        float pf[4][4];
        float s0 = 0.f, s1 = 0.f;
#pragma unroll
        for (int nt = 0; nt < 4; ++nt) {
            pf[nt][0] = __expf(sc[nt][0] - m0n);
            pf[nt][1] = __expf(sc[nt][1] - m0n);
            pf[nt][2] = __expf(sc[nt][2] - m1n);
            pf[nt][3] = __expf(sc[nt][3] - m1n);
            s0 += pf[nt][0] + pf[nt][1];
            s1 += pf[nt][2] + pf[nt][3];
        }
        s0 += __shfl_xor_sync(0xffffffffu, s0, 1);
        s0 += __shfl_xor_sync(0xffffffffu, s0, 2);
        s1 += __shfl_xor_sync(0xffffffffu, s1, 1);
        s1 += __shfl_xor_sync(0xffffffffu, s1, 2);

        l0 = l0 * a0 + s0;
        l1 = l1 * a1 + s1;
        m0 = m0n;
        m1 = m1n;

#pragma unroll
        for (int dt = 0; dt < 8; ++dt) {
            oa[dt][0] *= a0;
            oa[dt][1] *= a0;
            oa[dt][2] *= a1;
            oa[dt][3] *= a1;
        }

        // ---- P a-fragments: direct pack of S c-fragments (no shuffles) ----
        uint32_t pa[2][4];
#pragma unroll
        for (int h = 0; h < 2; ++h) {
            pa[h][0] = packh2(pf[2 * h][0], pf[2 * h][1]);
            pa[h][1] = packh2(pf[2 * h][2], pf[2 * h][3]);
            pa[h][2] = packh2(pf[2 * h + 1][0], pf[2 * h + 1][1]);
            pa[h][3] = packh2(pf[2 * h + 1][2], pf[2 * h + 1][3]);
        }

        // ---- PV: O += P V via m16n8k16 fp16 ----
#pragma unroll
        for (int ks2 = 0; ks2 < 2; ++ks2) {
#pragma unroll
            for (int dt = 0; dt < 8; ++dt) {
                uint32_t b[2];
                b[0] = Vw[stage][ks2 * 8 + tg][dt * 8 + gid];
                b[1] = Vw[stage][ks2 * 8 + tg + 4][dt * 8 + gid];
                mma_f16(oa[dt], pa[ks2], b);
            }
        }

        // ---- store prefetched tile into the other stage ----
        if (has_next) {
            const int ns = stage ^ 1;
            *(int4*)&Kw[ns][kr_][kw_] = kf;
            uint32_t w[4];
            w[0] = packh2(va.x, vb.x);
            w[1] = packh2(va.y, vb.y);
            w[2] = packh2(va.z, vb.z);
            w[3] = packh2(va.w, vb.w);
            *(int4*)&Vw[ns][vr_][vw_] = *(int4*)w;
        }
        __syncthreads();
    }

    // ---- epilogue (tf32 bits for the Wo GEMM) ----
    const float il0 = 1.0f / l0;
    const float il1 = 1.0f / l1;
#pragma unroll
    for (int dt = 0; dt < 8; ++dt) {
        const int cc = dt * 8 + 2 * tg;
        *(float2*)&o[base + (size_t)qrow0 * rs + cc] =
            make_float2(f2tf32f(oa[dt][0] * il0), f2tf32f(oa[dt][1] * il0));
        *(float2*)&o[base + (size_t)qrow1 * rs + cc] =
            make_float2(f2tf32f(oa[dt][2] * il1), f2tf32f(oa[dt][3] * il1));
    }
}

// ---------------------------------------------------------------------------
// Launch
// ---------------------------------------------------------------------------
extern "C" void kernel_launch(void* const* d_in, const int* in_sizes, int n_in,
                              void* d_out, int out_size) {
    (void)in_sizes; (void)n_in; (void)out_size;
    const float* Q  = (const float*)d_in[0];
    const float* K  = (const float*)d_in[1];
    const float* V  = (const float*)d_in[2];
    const float* Wq = (const float*)d_in[4];
    const float* Wk = (const float*)d_in[5];
    const float* Wv = (const float*)d_in[6];
    const float* Wo = (const float*)d_in[7];
    float* out = (float*)d_out;

    float *gq, *gk, *gv, *gvals, *qi, *ki, *vi, *wt;
    __half* kh;
    cudaGetSymbolAddress((void**)&gq, g_q);
    cudaGetSymbolAddress((void**)&gk, g_k);
    cudaGetSymbolAddress((void**)&gv, g_v);
    cudaGetSymbolAddress((void**)&gvals, g_vals);
    cudaGetSymbolAddress((void**)&qi, g_qi);
    cudaGetSymbolAddress((void**)&ki, g_ki);
    cudaGetSymbolAddress((void**)&vi, g_vi);
    cudaGetSymbolAddress((void**)&wt, g_wt);
    cudaGetSymbolAddress((void**)&kh, g_kh);

    cudaFuncSetAttribute(sgemm_tf32_v7,
                         cudaFuncAttributeMaxDynamicSharedMemorySize,
                         GEMM_SMEM7);

    const int M = MT;  // 4096

    // 0) pre-convert inputs + weights to tf32 bits
    dim3 pgrid(MT * CD / 4 / 256, 7);
    prep_cvt<<<pgrid, 256>>>(Q, K, V, Wq, Wk, Wv, Wo, qi, ki, vi, wt);

    // 1) QKV projections (all fp32 outputs)
    dim3 ggrid3(CD / BN, M / BM, 3);
    sgemm_tf32_v7<<<ggrid3, 128, GEMM_SMEM7>>>(
        qi, ki, vi, wt, wt + CD * CD, wt + 2 * CD * CD, gq, gk, gv, M, CD, CD,
        0);

    // 2) rope+rms (q in place fp32; k written as fp16)
    const int nwarps = CB * CS * CH;
    dim3 rgrid(nwarps / 8, 2);
    rope_rms_kernel<<<rgrid, 256>>>(gq, gk, kh);

    // 3) attention (fp16 tensor cores; writes tf32 bits)
    dim3 agrid(CS / 128, CB * CH);
    flash_attn_f16<<<agrid, 256>>>(gq, kh, gv, gvals);

    // 4) output projection (fp32 out)
    dim3 ggrid1(CD / BN, M / BM, 1);
    sgemm_tf32_v7<<<ggrid1, 128, GEMM_SMEM7>>>(
        gvals, nullptr, nullptr, wt + 3 * CD * CD, nullptr, nullptr, out,
        nullptr, nullptr, M, CD, CD, 0);
}

// round 13
// speedup vs baseline: 1.8643x; 1.3523x over previous
#include <cuda_runtime.h>
#include <cuda_bf16.h>
#include <cuda_fp16.h>
#include <math.h>
#include <stdint.h>

// Problem constants
constexpr int CB  = 2;
constexpr int CS  = 2048;
constexpr int CD  = 1024;
constexpr int CH  = 16;
constexpr int CHD = 64;
constexpr int MT  = CB * CS;  // 4096

// Scratch (allocation-free rule: static __device__ arrays)
__device__ __align__(256) float  g_q[MT * CD];
__device__ __align__(256) float  g_k[MT * CD];
__device__ __align__(256) float  g_v[MT * CD];
__device__ __align__(256) __half g_vals_h[MT * CD];  // attention out (fp16)
__device__ __align__(256) __half g_qh[MT * CD];      // fp16 inputs
__device__ __align__(256) __half g_kih[MT * CD];
__device__ __align__(256) __half g_vih[MT * CD];
__device__ __align__(256) uint32_t g_ww[4 * CD / 2 * CD];  // fp16 pair-words W
__device__ __align__(256) __half g_kh[MT * CD];      // fp16 K after rope+rms

// ---------------------------------------------------------------------------
// Helpers
// ---------------------------------------------------------------------------
__device__ __forceinline__ uint32_t packh2(float lo, float hi) {
    __half2 h = __floats2half2_rn(lo, hi);
    return *(uint32_t*)&h;
}

__device__ __forceinline__ void mma_f16(float c[4], const uint32_t a[4],
                                        const uint32_t b[2]) {
    asm volatile(
        "mma.sync.aligned.m16n8k16.row.col.f32.f16.f16.f32 "
        "{%0,%1,%2,%3}, {%4,%5,%6,%7}, {%8,%9}, {%0,%1,%2,%3};"
        : "+f"(c[0]), "+f"(c[1]), "+f"(c[2]), "+f"(c[3])
        : "r"(a[0]), "r"(a[1]), "r"(a[2]), "r"(a[3]), "r"(b[0]), "r"(b[1]));
}

__device__ __forceinline__ uint32_t smem_u32(const void* p) {
    uint32_t a;
    asm("{ .reg .u64 t; cvta.to.shared.u64 t, %1; cvt.u32.u64 %0, t; }"
        : "=r"(a) : "l"(p));
    return a;
}

__device__ __forceinline__ void cp16(uint32_t dst, const void* src) {
    asm volatile("cp.async.cg.shared.global [%0], [%1], 16;"
                 :: "r"(dst), "l"(src) : "memory");
}
#define CP_COMMIT() asm volatile("cp.async.commit_group;" ::: "memory")
#define CP_WAIT1()  asm volatile("cp.async.wait_group 1;" ::: "memory")

// ---------------------------------------------------------------------------
// prep: activations -> fp16 row-major; weights -> fp16 k-pair-interleaved
// words Ww[k/2][n] = (W[2k][n], W[2k+1][n]).  blockIdx.y: 0..2 act, 3..6 W.
// ---------------------------------------------------------------------------
__global__ __launch_bounds__(256) void prep_cvt(
    const float* __restrict__ Q, const float* __restrict__ K,
    const float* __restrict__ V, const float* __restrict__ Wq,
    const float* __restrict__ Wk, const float* __restrict__ Wv,
    const float* __restrict__ Wo, __half* __restrict__ qh,
    __half* __restrict__ kih, __half* __restrict__ vih,
    uint32_t* __restrict__ ww) {
    const int y = blockIdx.y;
    const int i = blockIdx.x * 256 + threadIdx.x;
    if (y < 3) {
        const float* src = (y == 0) ? Q : (y == 1) ? K : V;
        __half* dst = (y == 0) ? qh : (y == 1) ? kih : vih;
        if (i >= MT * CD / 4) return;
        float4 v = ((const float4*)src)[i];
        uint32_t w[2];
        w[0] = packh2(v.x, v.y);
        w[1] = packh2(v.z, v.w);
        *(uint2*)&dst[(size_t)i * 4] = *(uint2*)w;
    } else {
        const int wsel = y - 3;
        const float* W = (wsel == 0) ? Wq : (wsel == 1) ? Wk : (wsel == 2) ? Wv : Wo;
        uint32_t* dst = ww + (size_t)wsel * (CD / 2) * CD;
        if (i >= CD * CD / 8) return;  // each thread: 2 rows x 4 cols
        const int kp = i / (CD / 4);
        const int n  = (i % (CD / 4)) * 4;
        const float4 a = *(const float4*)&W[(size_t)(2 * kp) * CD + n];
        const float4 b = *(const float4*)&W[(size_t)(2 * kp + 1) * CD + n];
        uint32_t w[4];
        w[0] = packh2(a.x, b.x);
        w[1] = packh2(a.y, b.y);
        w[2] = packh2(a.z, b.z);
        w[3] = packh2(a.w, b.w);
        *(int4*)&dst[(size_t)kp * CD + n] = *(int4*)w;
    }
}

// ---------------------------------------------------------------------------
// fp16 tensor-core GEMM v8: m16n8k16, cp.async 3-stage, BK=32, 128 threads
// (4 warps, 64x64 warp tiles). A fp16 row-major; W fp16 pair-interleaved.
// C[M,N] fp32 = A[M,K] * W[K,N]. CTA tile 128x128.
// ---------------------------------------------------------------------------
constexpr int BM = 128, BN = 128;
constexpr int APADW = 20;                  // words per A row (16 used)
constexpr int BPADW = 136;                 // words per B pair-row (128 used)
constexpr int ABYTES = BM * APADW * 4;     // 10240
constexpr int BBYTES = 16 * BPADW * 4;     // 8704
constexpr int STAGEB = ABYTES + BBYTES;    // 18944
constexpr int GEMM_SMEM8 = 3 * STAGEB;     // 56832

__global__ __launch_bounds__(128) void hgemm_v8(
    const __half* __restrict__ A0, const __half* __restrict__ A1,
    const __half* __restrict__ A2, const uint32_t* __restrict__ WW,
    int wbase, float* __restrict__ C0, float* __restrict__ C1,
    float* __restrict__ C2, int M, int N, int K) {
    extern __shared__ char smem[];
    const uint32_t sb = smem_u32(smem);

    const int z = blockIdx.z;
    const __half* A = (z == 0) ? A0 : (z == 1) ? A1 : A2;
    const uint32_t* Wp = WW + (size_t)(wbase + z) * (CD / 2) * CD;
    float* C = (z == 0) ? C0 : (z == 1) ? C1 : C2;

    const int t    = threadIdx.x;
    const int lane = t & 31;
    const int warp = t >> 5;
    const int wm   = warp & 1;
    const int wn   = warp >> 1;
    const int gid  = lane >> 2;
    const int tg   = lane & 3;

    const int m0b = blockIdx.y * BM;
    const int n0b = blockIdx.x * BN;

    const int NC = K / 32;

    float c[4][8][4];
#pragma unroll
    for (int mt = 0; mt < 4; ++mt)
#pragma unroll
        for (int nt = 0; nt < 8; ++nt)
#pragma unroll
            for (int i = 0; i < 4; ++i) c[mt][nt][i] = 0.f;

    // fill one stage: A 128 rows x 4 segs(16B); B 16 pair-rows x 32 segs
    auto issue = [&](int ck, int s) {
        const int kn = ck * 32;
        const uint32_t abase = sb + s * STAGEB;
        const uint32_t bbase = abase + ABYTES;
#pragma unroll
        for (int i = 0; i < 4; ++i) {
            const int ci = t + i * 128;
            const int ar = ci >> 2, as = ci & 3;
            cp16(abase + ar * (APADW * 4) + as * 16,
                 &A[(size_t)(m0b + ar) * K + kn + as * 8]);
            const int br = ci >> 5, bs = ci & 31;
            cp16(bbase + (br * BPADW + bs * 4) * 4,
                 &Wp[(size_t)(kn / 2 + br) * N + n0b + bs * 4]);
        }
        CP_COMMIT();
    };

    issue(0, 0);
    issue(1, 1);

    for (int ck = 0; ck < NC; ++ck) {
        CP_WAIT1();
        __syncthreads();
        if (ck + 2 < NC) issue(ck + 2, (ck + 2) % 3);

        const int s = ck % 3;
        const uint32_t* As = (const uint32_t*)(smem + s * STAGEB);
        const uint32_t* Bs = (const uint32_t*)(smem + s * STAGEB + ABYTES);

#pragma unroll
        for (int ks = 0; ks < 2; ++ks) {  // two k16 steps per BK=32
            uint32_t af[4][4], bf[8][2];
#pragma unroll
            for (int mt = 0; mt < 4; ++mt) {
                const int mm = wm * 64 + mt * 16 + gid;
                af[mt][0] = As[mm * APADW + ks * 8 + tg];
                af[mt][1] = As[(mm + 8) * APADW + ks * 8 + tg];
                af[mt][2] = As[mm * APADW + ks * 8 + tg + 4];
                af[mt][3] = As[(mm + 8) * APADW + ks * 8 + tg + 4];
            }
#pragma unroll
            for (int nt = 0; nt < 8; ++nt) {
                const int nn = wn * 64 + nt * 8 + gid;
                bf[nt][0] = Bs[(ks * 8 + tg) * BPADW + nn];
                bf[nt][1] = Bs[(ks * 8 + tg + 4) * BPADW + nn];
            }
#pragma unroll
            for (int mt = 0; mt < 4; ++mt)
#pragma unroll
                for (int nt = 0; nt < 8; ++nt) mma_f16(c[mt][nt], af[mt], bf[nt]);
        }
    }

    // epilogue (fp32)
#pragma unroll
    for (int mt = 0; mt < 4; ++mt) {
        const int r0 = m0b + wm * 64 + mt * 16 + gid;
#pragma unroll
        for (int nt = 0; nt < 8; ++nt) {
            const int cc = n0b + wn * 64 + nt * 8 + tg * 2;
            *(float2*)&C[(size_t)r0 * N + cc]       = make_float2(c[mt][nt][0], c[mt][nt][1]);
            *(float2*)&C[(size_t)(r0 + 8) * N + cc] = make_float2(c[mt][nt][2], c[mt][nt][3]);
        }
    }
}

// ---------------------------------------------------------------------------
// RoPE (bf16 cos/sin tables) + RMSNorm. blockIdx.y: 0=q (in place fp32),
// 1=k (writes fp16 to kh buffer for the fp16 attention).
// ---------------------------------------------------------------------------
__global__ __launch_bounds__(256) void rope_rms_kernel(float* __restrict__ xq,
                                                       float* __restrict__ xk,
                                                       __half* __restrict__ kh) {
    const bool isk = blockIdx.y;
    float* x = isk ? xk : xq;
    const int gt   = blockIdx.x * blockDim.x + threadIdx.x;
    const int gw   = gt >> 5;
    const int lane = gt & 31;
    if (gw >= CB * CS * CH) return;

    const int sPos = (gw / CH) % CS;
    float* p = x + (size_t)gw * CHD;

    const float x1 = p[lane];
    const float x2 = p[lane + 32];

    const float ex = (float)(2 * lane) * (1.0f / 64.0f);
    const float fr = powf(100000.0f, ex);
    const float g  = (float)sPos * (1.0f / fr);
    const float cc = __bfloat162float(__float2bfloat16(cosf(g)));
    const float sn = __bfloat162float(__float2bfloat16(sinf(g)));

    const float y1 = x1 * cc + x2 * sn;
    const float y2 = -x1 * sn + x2 * cc;

    float ss = y1 * y1 + y2 * y2;
#pragma unroll
    for (int o = 16; o > 0; o >>= 1) ss += __shfl_xor_sync(0xffffffffu, ss, o);

    const float rms = sqrtf(ss * (1.0f / 64.0f) + 1e-9f);
    const float ir  = 1.0f / rms;
    const float o1 = y1 * ir, o2 = y2 * ir;
    if (isk) {
        __half* ph = kh + (size_t)gw * CHD;
        ph[lane]      = __float2half_rn(o1);
        ph[lane + 32] = __float2half_rn(o2);
    } else {
        p[lane]      = o1;
        p[lane + 32] = o2;
    }
}

// ---------------------------------------------------------------------------
// Causal flash attention with fp16 m16n8k16 tensor cores (fp32 accumulate).
// Output written as fp16 (A operand of the Wo GEMM).
// ---------------------------------------------------------------------------
__global__ __launch_bounds__(256, 2) void flash_attn_f16(
    const float* __restrict__ q, const __half* __restrict__ kh,
    const float* __restrict__ v, __half* __restrict__ o) {
    __shared__ uint32_t Kw[2][32][36];
    __shared__ uint32_t Vw[2][16][72];

    const int t    = threadIdx.x;
    const int lane = t & 31;
    const int warp = t >> 5;
    const int gid  = lane >> 2;
    const int tg   = lane & 3;

    const int q0 = (gridDim.x - 1 - blockIdx.x) * 128;
    const int bh = blockIdx.y;
    const size_t base = ((size_t)(bh >> 4) * CS * CH + (bh & 15)) * CHD;
    const int rs = CH * CHD;

    const int qrow0 = q0 + warp * 16 + gid;
    const int qrow1 = qrow0 + 8;

    const int kr_ = t >> 3;
    const int kw_ = (t & 7) * 4;
    const int vr_ = t >> 4;
    const int vw_ = (t & 15) * 4;

    uint32_t qa[4][4];
#pragma unroll
    for (int ks = 0; ks < 4; ++ks) {
        const float2 x00 = *(const float2*)&q[base + (size_t)qrow0 * rs + ks * 16 + 2 * tg];
        const float2 x01 = *(const float2*)&q[base + (size_t)qrow0 * rs + ks * 16 + 8 + 2 * tg];
        const float2 x10 = *(const float2*)&q[base + (size_t)qrow1 * rs + ks * 16 + 2 * tg];
        const float2 x11 = *(const float2*)&q[base + (size_t)qrow1 * rs + ks * 16 + 8 + 2 * tg];
        qa[ks][0] = packh2(0.125f * x00.x, 0.125f * x00.y);
        qa[ks][1] = packh2(0.125f * x10.x, 0.125f * x10.y);
        qa[ks][2] = packh2(0.125f * x01.x, 0.125f * x01.y);
        qa[ks][3] = packh2(0.125f * x11.x, 0.125f * x11.y);
    }

    float oa[8][4];
#pragma unroll
    for (int dt = 0; dt < 8; ++dt)
#pragma unroll
        for (int i = 0; i < 4; ++i) oa[dt][i] = 0.f;

    float m0 = -1e30f, m1 = -1e30f, l0 = 0.f, l1 = 0.f;

    {
        *(int4*)&Kw[0][kr_][kw_] =
            *(const int4*)&kh[base + (size_t)kr_ * rs + kw_ * 2];
        const float4 va = *(const float4*)&v[base + (size_t)(2 * vr_) * rs + vw_];
        const float4 vb = *(const float4*)&v[base + (size_t)(2 * vr_ + 1) * rs + vw_];
        uint32_t w[4];
        w[0] = packh2(va.x, vb.x);
        w[1] = packh2(va.y, vb.y);
        w[2] = packh2(va.z, vb.z);
        w[3] = packh2(va.w, vb.w);
        *(int4*)&Vw[0][vr_][vw_] = *(int4*)w;
    }
    __syncthreads();

    const int nkt = (q0 >> 5) + 4;
    for (int kt = 0; kt < nkt; ++kt) {
        const int stage = kt & 1;
        const bool has_next = (kt + 1 < nkt);

        int4 kf;
        float4 va, vb;
        if (has_next) {
            const int kvn = (kt + 1) << 5;
            kf = *(const int4*)&kh[base + (size_t)(kvn + kr_) * rs + kw_ * 2];
            va = *(const float4*)&v[base + (size_t)(kvn + 2 * vr_) * rs + vw_];
            vb = *(const float4*)&v[base + (size_t)(kvn + 2 * vr_ + 1) * rs + vw_];
        }

        const int kv0 = kt << 5;

        float sc[4][4];
#pragma unroll
        for (int nt = 0; nt < 4; ++nt)
#pragma unroll
            for (int i = 0; i < 4; ++i) sc[nt][i] = 0.f;

#pragma unroll
        for (int ks = 0; ks < 4; ++ks) {
#pragma unroll
            for (int nt = 0; nt < 4; ++nt) {
                uint32_t b[2];
                b[0] = Kw[stage][nt * 8 + gid][ks * 8 + tg];
                b[1] = Kw[stage][nt * 8 + gid][ks * 8 + tg + 4];
                mma_f16(sc[nt], qa[ks], b);
            }
        }

        const bool needmask = (kv0 + 31 > qrow0);
        if (needmask) {
#pragma unroll
            for (int nt = 0; nt < 4; ++nt) {
                const int c0 = kv0 + nt * 8 + 2 * tg;
                const int c1 = c0 + 1;
                if (c0 > qrow0) sc[nt][0] = -1e9f;
                if (c1 > qrow0) sc[nt][1] = -1e9f;
                if (c0 > qrow1) sc[nt][2] = -1e9f;
                if (c1 > qrow1) sc[nt][3] = -1e9f;
            }
        }

        float tm0 = -1e30f, tm1 = -1e30f;
#pragma unroll
        for (int nt = 0; nt < 4; ++nt) {
            tm0 = fmaxf(tm0, fmaxf(sc[nt][0], sc[nt][1]));
            tm1 = fmaxf(tm1, fmaxf(sc[nt][2], sc[nt][3]));
        }
        tm0 = fmaxf(tm0, __shfl_xor_sync(0xffffffffu, tm0, 1));
        tm0 = fmaxf(tm0, __shfl_xor_sync(0xffffffffu, tm0, 2));
        tm1 = fmaxf(tm1, __shfl_xor_sync(0xffffffffu, tm1, 1));
        tm1 = fmaxf(tm1, __shfl_xor_sync(0xffffffffu, tm1, 2));

        const float m0n = fmaxf(m0, tm0);
        const float m1n = fmaxf(m1, tm1);
        const float a0  = __expf(m0 - m0n);
        const float a1  = __expf(m1 - m1n);

        float pf[4][4];
        float s0 = 0.f, s1 = 0.f;
#pragma unroll
        for (int nt = 0; nt < 4; ++nt) {
            pf[nt][0] = __expf(sc[nt][0] - m0n);
            pf[nt][1] = __expf(sc[nt][1] - m0n);
            pf[nt][2] = __expf(sc[nt][2] - m1n);
            pf[nt][3] = __expf(sc[nt][3] - m1n);
            s0 += pf[nt][0] + pf[nt][1];
            s1 += pf[nt][2] + pf[nt][3];
        }
        s0 += __shfl_xor_sync(0xffffffffu, s0, 1);
        s0 += __shfl_xor_sync(0xffffffffu, s0, 2);
        s1 += __shfl_xor_sync(0xffffffffu, s1, 1);
        s1 += __shfl_xor_sync(0xffffffffu, s1, 2);

        l0 = l0 * a0 + s0;
        l1 = l1 * a1 + s1;
        m0 = m0n;
        m1 = m1n;

#pragma unroll
        for (int dt = 0; dt < 8; ++dt) {
            oa[dt][0] *= a0;
            oa[dt][1] *= a0;
            oa[dt][2] *= a1;
            oa[dt][3] *= a1;
        }

        uint32_t pa[2][4];
#pragma unroll
        for (int h = 0; h < 2; ++h) {
            pa[h][0] = packh2(pf[2 * h][0], pf[2 * h][1]);
            pa[h][1] = packh2(pf[2 * h][2], pf[2 * h][3]);
            pa[h][2] = packh2(pf[2 * h + 1][0], pf[2 * h + 1][1]);
            pa[h][3] = packh2(pf[2 * h + 1][2], pf[2 * h + 1][3]);
        }

#pragma unroll
        for (int ks2 = 0; ks2 < 2; ++ks2) {
#pragma unroll
            for (int dt = 0; dt < 8; ++dt) {
                uint32_t b[2];
                b[0] = Vw[stage][ks2 * 8 + tg][dt * 8 + gid];
                b[1] = Vw[stage][ks2 * 8 + tg + 4][dt * 8 + gid];
                mma_f16(oa[dt], pa[ks2], b);
            }
        }

        if (has_next) {
            const int ns = stage ^ 1;
            *(int4*)&Kw[ns][kr_][kw_] = kf;
            uint32_t w[4];
            w[0] = packh2(va.x, vb.x);
            w[1] = packh2(va.y, vb.y);
            w[2] = packh2(va.z, vb.z);
            w[3] = packh2(va.w, vb.w);
            *(int4*)&Vw[ns][vr_][vw_] = *(int4*)w;
        }
        __syncthreads();
    }

    // ---- epilogue: fp16 (A operand of the Wo GEMM) ----
    const float il0 = 1.0f / l0;
    const float il1 = 1.0f / l1;
#pragma unroll
    for (int dt = 0; dt < 8; ++dt) {
        const int cc = dt * 8 + 2 * tg;
        *(uint32_t*)&o[base + (size_t)qrow0 * rs + cc] =
            packh2(oa[dt][0] * il0, oa[dt][1] * il0);
        *(uint32_t*)&o[base + (size_t)qrow1 * rs + cc] =
            packh2(oa[dt][2] * il1, oa[dt][3] * il1);
    }
}

// ---------------------------------------------------------------------------
// Launch
// ---------------------------------------------------------------------------
extern "C" void kernel_launch(void* const* d_in, const int* in_sizes, int n_in,
                              void* d_out, int out_size) {
    (void)in_sizes; (void)n_in; (void)out_size;
    const float* Q  = (const float*)d_in[0];
    const float* K  = (const float*)d_in[1];
    const float* V  = (const float*)d_in[2];
    const float* Wq = (const float*)d_in[4];
    const float* Wk = (const float*)d_in[5];
    const float* Wv = (const float*)d_in[6];
    const float* Wo = (const float*)d_in[7];
    float* out = (float*)d_out;

    float *gq, *gk, *gv;
    __half *gvals_h, *qh, *kih, *vih, *kh;
    uint32_t* ww;
    cudaGetSymbolAddress((void**)&gq, g_q);
    cudaGetSymbolAddress((void**)&gk, g_k);
    cudaGetSymbolAddress((void**)&gv, g_v);
    cudaGetSymbolAddress((void**)&gvals_h, g_vals_h);
    cudaGetSymbolAddress((void**)&qh, g_qh);
    cudaGetSymbolAddress((void**)&kih, g_kih);
    cudaGetSymbolAddress((void**)&vih, g_vih);
    cudaGetSymbolAddress((void**)&ww, g_ww);
    cudaGetSymbolAddress((void**)&kh, g_kh);

    cudaFuncSetAttribute(hgemm_v8, cudaFuncAttributeMaxDynamicSharedMemorySize,
                         GEMM_SMEM8);

    const int M = MT;  // 4096

    // 0) pre-convert inputs + weights to fp16 (weights pair-interleaved)
    dim3 pgrid(MT * CD / 4 / 256, 7);  // y<3 uses all; y>=3 bounded inside
    prep_cvt<<<pgrid, 256>>>(Q, K, V, Wq, Wk, Wv, Wo, qh, kih, vih, ww);

    // 1) QKV projections (fp16 in, fp32 out)
    dim3 ggrid3(CD / BN, M / BM, 3);
    hgemm_v8<<<ggrid3, 128, GEMM_SMEM8>>>(qh, kih, vih, ww, 0, gq, gk, gv, M,
                                          CD, CD);

    // 2) rope+rms (q in place fp32; k written as fp16)
    const int nwarps = CB * CS * CH;
    dim3 rgrid(nwarps / 8, 2);
    rope_rms_kernel<<<rgrid, 256>>>(gq, gk, kh);

    // 3) attention (fp16 tensor cores; writes fp16)
    dim3 agrid(CS / 128, CB * CH);
    flash_attn_f16<<<agrid, 256>>>(gq, kh, gv, gvals_h);

    // 4) output projection (fp16 in, fp32 out)
    dim3 ggrid1(CD / BN, M / BM, 1);
    hgemm_v8<<<ggrid1, 128, GEMM_SMEM8>>>(gvals_h, nullptr, nullptr, ww, 3,
                                          out, nullptr, nullptr, M, CD, CD);
}

// round 14
// speedup vs baseline: 1.9892x; 1.0670x over previous
#include <cuda_runtime.h>
#include <cuda_bf16.h>
#include <cuda_fp16.h>
#include <math.h>
#include <stdint.h>

// Problem constants
constexpr int CB  = 2;
constexpr int CS  = 2048;
constexpr int CD  = 1024;
constexpr int CH  = 16;
constexpr int CHD = 64;
constexpr int MT  = CB * CS;  // 4096

// Scratch (allocation-free rule: static __device__ arrays)
__device__ __align__(256) float  g_q[MT * CD];
__device__ __align__(256) float  g_k[MT * CD];
__device__ __align__(256) float  g_v[MT * CD];
__device__ __align__(256) __half g_vals_h[MT * CD];  // attention out (fp16)
__device__ __align__(256) __half g_qh[MT * CD];      // fp16 inputs
__device__ __align__(256) __half g_kih[MT * CD];
__device__ __align__(256) __half g_vih[MT * CD];
__device__ __align__(256) uint32_t g_ww[4 * CD / 2 * CD];  // fp16 pair-words W
__device__ __align__(256) __half g_kh[MT * CD];      // fp16 K after rope+rms

// ---------------------------------------------------------------------------
// Helpers
// ---------------------------------------------------------------------------
__device__ __forceinline__ uint32_t packh2(float lo, float hi) {
    __half2 h = __floats2half2_rn(lo, hi);
    return *(uint32_t*)&h;
}

__device__ __forceinline__ float ex2(float x) {
    float r;
    asm("ex2.approx.f32 %0, %1;" : "=f"(r) : "f"(x));
    return r;
}

__device__ __forceinline__ void mma_f16(float c[4], const uint32_t a[4],
                                        const uint32_t b[2]) {
    asm volatile(
        "mma.sync.aligned.m16n8k16.row.col.f32.f16.f16.f32 "
        "{%0,%1,%2,%3}, {%4,%5,%6,%7}, {%8,%9}, {%0,%1,%2,%3};"
        : "+f"(c[0]), "+f"(c[1]), "+f"(c[2]), "+f"(c[3])
        : "r"(a[0]), "r"(a[1]), "r"(a[2]), "r"(a[3]), "r"(b[0]), "r"(b[1]));
}

__device__ __forceinline__ uint32_t smem_u32(const void* p) {
    uint32_t a;
    asm("{ .reg .u64 t; cvta.to.shared.u64 t, %1; cvt.u32.u64 %0, t; }"
        : "=r"(a) : "l"(p));
    return a;
}

__device__ __forceinline__ void cp16(uint32_t dst, const void* src) {
    asm volatile("cp.async.cg.shared.global [%0], [%1], 16;"
                 :: "r"(dst), "l"(src) : "memory");
}
#define CP_COMMIT() asm volatile("cp.async.commit_group;" ::: "memory")
#define CP_WAIT1()  asm volatile("cp.async.wait_group 1;" ::: "memory")

// ---------------------------------------------------------------------------
// prep: activations -> fp16 row-major; weights -> fp16 k-pair-interleaved
// words Ww[k/2][n] = (W[2k][n], W[2k+1][n]).  blockIdx.y: 0..2 act, 3..6 W.
// ---------------------------------------------------------------------------
__global__ __launch_bounds__(256) void prep_cvt(
    const float* __restrict__ Q, const float* __restrict__ K,
    const float* __restrict__ V, const float* __restrict__ Wq,
    const float* __restrict__ Wk, const float* __restrict__ Wv,
    const float* __restrict__ Wo, __half* __restrict__ qh,
    __half* __restrict__ kih, __half* __restrict__ vih,
    uint32_t* __restrict__ ww) {
    const int y = blockIdx.y;
    const int i = blockIdx.x * 256 + threadIdx.x;
    if (y < 3) {
        const float* src = (y == 0) ? Q : (y == 1) ? K : V;
        __half* dst = (y == 0) ? qh : (y == 1) ? kih : vih;
        if (i >= MT * CD / 4) return;
        float4 v = ((const float4*)src)[i];
        uint32_t w[2];
        w[0] = packh2(v.x, v.y);
        w[1] = packh2(v.z, v.w);
        *(uint2*)&dst[(size_t)i * 4] = *(uint2*)w;
    } else {
        const int wsel = y - 3;
        const float* W = (wsel == 0) ? Wq : (wsel == 1) ? Wk : (wsel == 2) ? Wv : Wo;
        uint32_t* dst = ww + (size_t)wsel * (CD / 2) * CD;
        if (i >= CD * CD / 8) return;
        const int kp = i / (CD / 4);
        const int n  = (i % (CD / 4)) * 4;
        const float4 a = *(const float4*)&W[(size_t)(2 * kp) * CD + n];
        const float4 b = *(const float4*)&W[(size_t)(2 * kp + 1) * CD + n];
        uint32_t w[4];
        w[0] = packh2(a.x, b.x);
        w[1] = packh2(a.y, b.y);
        w[2] = packh2(a.z, b.z);
        w[3] = packh2(a.w, b.w);
        *(int4*)&dst[(size_t)kp * CD + n] = *(int4*)w;
    }
}

// ---------------------------------------------------------------------------
// fp16 tensor-core GEMM v8: m16n8k16, cp.async 3-stage, BK=32, 128 threads
// (4 warps, 64x64 warp tiles). A fp16 row-major; W fp16 pair-interleaved.
// ---------------------------------------------------------------------------
constexpr int BM = 128, BN = 128;
constexpr int APADW = 20;
constexpr int BPADW = 136;
constexpr int ABYTES = BM * APADW * 4;
constexpr int BBYTES = 16 * BPADW * 4;
constexpr int STAGEB = ABYTES + BBYTES;
constexpr int GEMM_SMEM8 = 3 * STAGEB;  // 56832

__global__ __launch_bounds__(128) void hgemm_v8(
    const __half* __restrict__ A0, const __half* __restrict__ A1,
    const __half* __restrict__ A2, const uint32_t* __restrict__ WW,
    int wbase, float* __restrict__ C0, float* __restrict__ C1,
    float* __restrict__ C2, int M, int N, int K) {
    extern __shared__ char smem[];
    const uint32_t sb = smem_u32(smem);

    const int z = blockIdx.z;
    const __half* A = (z == 0) ? A0 : (z == 1) ? A1 : A2;
    const uint32_t* Wp = WW + (size_t)(wbase + z) * (CD / 2) * CD;
    float* C = (z == 0) ? C0 : (z == 1) ? C1 : C2;

    const int t    = threadIdx.x;
    const int lane = t & 31;
    const int warp = t >> 5;
    const int wm   = warp & 1;
    const int wn   = warp >> 1;
    const int gid  = lane >> 2;
    const int tg   = lane & 3;

    const int m0b = blockIdx.y * BM;
    const int n0b = blockIdx.x * BN;

    const int NC = K / 32;

    float c[4][8][4];
#pragma unroll
    for (int mt = 0; mt < 4; ++mt)
#pragma unroll
        for (int nt = 0; nt < 8; ++nt)
#pragma unroll
            for (int i = 0; i < 4; ++i) c[mt][nt][i] = 0.f;

    auto issue = [&](int ck, int s) {
        const int kn = ck * 32;
        const uint32_t abase = sb + s * STAGEB;
        const uint32_t bbase = abase + ABYTES;
#pragma unroll
        for (int i = 0; i < 4; ++i) {
            const int ci = t + i * 128;
            const int ar = ci >> 2, as = ci & 3;
            cp16(abase + ar * (APADW * 4) + as * 16,
                 &A[(size_t)(m0b + ar) * K + kn + as * 8]);
            const int br = ci >> 5, bs = ci & 31;
            cp16(bbase + (br * BPADW + bs * 4) * 4,
                 &Wp[(size_t)(kn / 2 + br) * N + n0b + bs * 4]);
        }
        CP_COMMIT();
    };

    issue(0, 0);
    issue(1, 1);

    for (int ck = 0; ck < NC; ++ck) {
        CP_WAIT1();
        __syncthreads();
        if (ck + 2 < NC) issue(ck + 2, (ck + 2) % 3);

        const int s = ck % 3;
        const uint32_t* As = (const uint32_t*)(smem + s * STAGEB);
        const uint32_t* Bs = (const uint32_t*)(smem + s * STAGEB + ABYTES);

#pragma unroll
        for (int ks = 0; ks < 2; ++ks) {
            uint32_t af[4][4], bf[8][2];
#pragma unroll
            for (int mt = 0; mt < 4; ++mt) {
                const int mm = wm * 64 + mt * 16 + gid;
                af[mt][0] = As[mm * APADW + ks * 8 + tg];
                af[mt][1] = As[(mm + 8) * APADW + ks * 8 + tg];
                af[mt][2] = As[mm * APADW + ks * 8 + tg + 4];
                af[mt][3] = As[(mm + 8) * APADW + ks * 8 + tg + 4];
            }
#pragma unroll
            for (int nt = 0; nt < 8; ++nt) {
                const int nn = wn * 64 + nt * 8 + gid;
                bf[nt][0] = Bs[(ks * 8 + tg) * BPADW + nn];
                bf[nt][1] = Bs[(ks * 8 + tg + 4) * BPADW + nn];
            }
#pragma unroll
            for (int mt = 0; mt < 4; ++mt)
#pragma unroll
                for (int nt = 0; nt < 8; ++nt) mma_f16(c[mt][nt], af[mt], bf[nt]);
        }
    }

#pragma unroll
    for (int mt = 0; mt < 4; ++mt) {
        const int r0 = m0b + wm * 64 + mt * 16 + gid;
#pragma unroll
        for (int nt = 0; nt < 8; ++nt) {
            const int cc = n0b + wn * 64 + nt * 8 + tg * 2;
            *(float2*)&C[(size_t)r0 * N + cc]       = make_float2(c[mt][nt][0], c[mt][nt][1]);
            *(float2*)&C[(size_t)(r0 + 8) * N + cc] = make_float2(c[mt][nt][2], c[mt][nt][3]);
        }
    }
}

// ---------------------------------------------------------------------------
// RoPE (bf16 cos/sin tables) + RMSNorm. blockIdx.y: 0=q (in place fp32),
// 1=k (writes fp16 to kh buffer).
// ---------------------------------------------------------------------------
__global__ __launch_bounds__(256) void rope_rms_kernel(float* __restrict__ xq,
                                                       float* __restrict__ xk,
                                                       __half* __restrict__ kh) {
    const bool isk = blockIdx.y;
    float* x = isk ? xk : xq;
    const int gt   = blockIdx.x * blockDim.x + threadIdx.x;
    const int gw   = gt >> 5;
    const int lane = gt & 31;
    if (gw >= CB * CS * CH) return;

    const int sPos = (gw / CH) % CS;
    float* p = x + (size_t)gw * CHD;

    const float x1 = p[lane];
    const float x2 = p[lane + 32];

    const float ex = (float)(2 * lane) * (1.0f / 64.0f);
    const float fr = powf(100000.0f, ex);
    const float g  = (float)sPos * (1.0f / fr);
    const float cc = __bfloat162float(__float2bfloat16(cosf(g)));
    const float sn = __bfloat162float(__float2bfloat16(sinf(g)));

    const float y1 = x1 * cc + x2 * sn;
    const float y2 = -x1 * sn + x2 * cc;

    float ss = y1 * y1 + y2 * y2;
#pragma unroll
    for (int o = 16; o > 0; o >>= 1) ss += __shfl_xor_sync(0xffffffffu, ss, o);

    const float rms = sqrtf(ss * (1.0f / 64.0f) + 1e-9f);
    const float ir  = 1.0f / rms;
    const float o1 = y1 * ir, o2 = y2 * ir;
    if (isk) {
        __half* ph = kh + (size_t)gw * CHD;
        ph[lane]      = __float2half_rn(o1);
        ph[lane + 32] = __float2half_rn(o2);
    } else {
        p[lane]      = o1;
        p[lane + 32] = o2;
    }
}

// ---------------------------------------------------------------------------
// Causal flash attention, fp16 m16n8k16, NO online max: after RMSNorm,
// |logit| <= ||q||*||k||/8 = 8, so exp(s) <= e^8 ~ 3000 — safe in fp16/fp32.
// p = exp2(s*log2e) directly (log2e/8 folded into Q fragments); O and l
// accumulate unnormalized; single normalization in the epilogue.
// ---------------------------------------------------------------------------
__global__ __launch_bounds__(256, 2) void flash_attn_f16(
    const float* __restrict__ q, const __half* __restrict__ kh,
    const float* __restrict__ v, __half* __restrict__ o) {
    __shared__ uint32_t Kw[2][32][36];
    __shared__ uint32_t Vw[2][16][72];

    const int t    = threadIdx.x;
    const int lane = t & 31;
    const int warp = t >> 5;
    const int gid  = lane >> 2;
    const int tg   = lane & 3;

    const int q0 = (gridDim.x - 1 - blockIdx.x) * 128;
    const int bh = blockIdx.y;
    const size_t base = ((size_t)(bh >> 4) * CS * CH + (bh & 15)) * CHD;
    const int rs = CH * CHD;

    const int qrow0 = q0 + warp * 16 + gid;
    const int qrow1 = qrow0 + 8;

    const int kr_ = t >> 3;
    const int kw_ = (t & 7) * 4;
    const int vr_ = t >> 4;
    const int vw_ = (t & 15) * 4;

    // Q fragments with 0.125 * log2(e) folded in (scores in log2 domain)
    const float QS = 0.125f * 1.4426950408889634f;
    uint32_t qa[4][4];
#pragma unroll
    for (int ks = 0; ks < 4; ++ks) {
        const float2 x00 = *(const float2*)&q[base + (size_t)qrow0 * rs + ks * 16 + 2 * tg];
        const float2 x01 = *(const float2*)&q[base + (size_t)qrow0 * rs + ks * 16 + 8 + 2 * tg];
        const float2 x10 = *(const float2*)&q[base + (size_t)qrow1 * rs + ks * 16 + 2 * tg];
        const float2 x11 = *(const float2*)&q[base + (size_t)qrow1 * rs + ks * 16 + 8 + 2 * tg];
        qa[ks][0] = packh2(QS * x00.x, QS * x00.y);
        qa[ks][1] = packh2(QS * x10.x, QS * x10.y);
        qa[ks][2] = packh2(QS * x01.x, QS * x01.y);
        qa[ks][3] = packh2(QS * x11.x, QS * x11.y);
    }

    float oa[8][4];
#pragma unroll
    for (int dt = 0; dt < 8; ++dt)
#pragma unroll
        for (int i = 0; i < 4; ++i) oa[dt][i] = 0.f;

    float l0 = 0.f, l1 = 0.f;

    {
        *(int4*)&Kw[0][kr_][kw_] =
            *(const int4*)&kh[base + (size_t)kr_ * rs + kw_ * 2];
        const float4 va = *(const float4*)&v[base + (size_t)(2 * vr_) * rs + vw_];
        const float4 vb = *(const float4*)&v[base + (size_t)(2 * vr_ + 1) * rs + vw_];
        uint32_t w[4];
        w[0] = packh2(va.x, vb.x);
        w[1] = packh2(va.y, vb.y);
        w[2] = packh2(va.z, vb.z);
        w[3] = packh2(va.w, vb.w);
        *(int4*)&Vw[0][vr_][vw_] = *(int4*)w;
    }
    __syncthreads();

    const int nkt = (q0 >> 5) + 4;
    for (int kt = 0; kt < nkt; ++kt) {
        const int stage = kt & 1;
        const bool has_next = (kt + 1 < nkt);

        int4 kf;
        float4 va, vb;
        if (has_next) {
            const int kvn = (kt + 1) << 5;
            kf = *(const int4*)&kh[base + (size_t)(kvn + kr_) * rs + kw_ * 2];
            va = *(const float4*)&v[base + (size_t)(kvn + 2 * vr_) * rs + vw_];
            vb = *(const float4*)&v[base + (size_t)(kvn + 2 * vr_ + 1) * rs + vw_];
        }

        const int kv0 = kt << 5;

        // ---- scores (log2 domain) ----
        float sc[4][4];
#pragma unroll
        for (int nt = 0; nt < 4; ++nt)
#pragma unroll
            for (int i = 0; i < 4; ++i) sc[nt][i] = 0.f;

#pragma unroll
        for (int ks = 0; ks < 4; ++ks) {
#pragma unroll
            for (int nt = 0; nt < 4; ++nt) {
                uint32_t b[2];
                b[0] = Kw[stage][nt * 8 + gid][ks * 8 + tg];
                b[1] = Kw[stage][nt * 8 + gid][ks * 8 + tg + 4];
                mma_f16(sc[nt], qa[ks], b);
            }
        }

        // ---- causal mask ----
        const bool needmask = (kv0 + 31 > qrow0);
        if (needmask) {
#pragma unroll
            for (int nt = 0; nt < 4; ++nt) {
                const int c0 = kv0 + nt * 8 + 2 * tg;
                const int c1 = c0 + 1;
                if (c0 > qrow0) sc[nt][0] = -1e9f;
                if (c1 > qrow0) sc[nt][1] = -1e9f;
                if (c0 > qrow1) sc[nt][2] = -1e9f;
                if (c1 > qrow1) sc[nt][3] = -1e9f;
            }
        }

        // ---- p = exp2(sc); accumulate row sums (no max, no rescale) ----
        float pf[4][4];
        float s0 = 0.f, s1 = 0.f;
#pragma unroll
        for (int nt = 0; nt < 4; ++nt) {
            pf[nt][0] = ex2(sc[nt][0]);
            pf[nt][1] = ex2(sc[nt][1]);
            pf[nt][2] = ex2(sc[nt][2]);
            pf[nt][3] = ex2(sc[nt][3]);
            s0 += pf[nt][0] + pf[nt][1];
            s1 += pf[nt][2] + pf[nt][3];
        }
        l0 += s0;
        l1 += s1;

        // ---- P a-fragments: direct pack (fp16 FA identity) ----
        uint32_t pa[2][4];
#pragma unroll
        for (int h = 0; h < 2; ++h) {
            pa[h][0] = packh2(pf[2 * h][0], pf[2 * h][1]);
            pa[h][1] = packh2(pf[2 * h][2], pf[2 * h][3]);
            pa[h][2] = packh2(pf[2 * h + 1][0], pf[2 * h + 1][1]);
            pa[h][3] = packh2(pf[2 * h + 1][2], pf[2 * h + 1][3]);
        }

        // ---- PV ----
#pragma unroll
        for (int ks2 = 0; ks2 < 2; ++ks2) {
#pragma unroll
            for (int dt = 0; dt < 8; ++dt) {
                uint32_t b[2];
                b[0] = Vw[stage][ks2 * 8 + tg][dt * 8 + gid];
                b[1] = Vw[stage][ks2 * 8 + tg + 4][dt * 8 + gid];
                mma_f16(oa[dt], pa[ks2], b);
            }
        }

        if (has_next) {
            const int ns = stage ^ 1;
            *(int4*)&Kw[ns][kr_][kw_] = kf;
            uint32_t w[4];
            w[0] = packh2(va.x, vb.x);
            w[1] = packh2(va.y, vb.y);
            w[2] = packh2(va.z, vb.z);
            w[3] = packh2(va.w, vb.w);
            *(int4*)&Vw[ns][vr_][vw_] = *(int4*)w;
        }
        __syncthreads();
    }

    // ---- row-sum reduction across quad + normalize + fp16 store ----
    l0 += __shfl_xor_sync(0xffffffffu, l0, 1);
    l0 += __shfl_xor_sync(0xffffffffu, l0, 2);
    l1 += __shfl_xor_sync(0xffffffffu, l1, 1);
    l1 += __shfl_xor_sync(0xffffffffu, l1, 2);
    const float il0 = 1.0f / l0;
    const float il1 = 1.0f / l1;
#pragma unroll
    for (int dt = 0; dt < 8; ++dt) {
        const int cc = dt * 8 + 2 * tg;
        *(uint32_t*)&o[base + (size_t)qrow0 * rs + cc] =
            packh2(oa[dt][0] * il0, oa[dt][1] * il0);
        *(uint32_t*)&o[base + (size_t)qrow1 * rs + cc] =
            packh2(oa[dt][2] * il1, oa[dt][3] * il1);
    }
}

// ---------------------------------------------------------------------------
// Launch
// ---------------------------------------------------------------------------
extern "C" void kernel_launch(void* const* d_in, const int* in_sizes, int n_in,
                              void* d_out, int out_size) {
    (void)in_sizes; (void)n_in; (void)out_size;
    const float* Q  = (const float*)d_in[0];
    const float* K  = (const float*)d_in[1];
    const float* V  = (const float*)d_in[2];
    const float* Wq = (const float*)d_in[4];
    const float* Wk = (const float*)d_in[5];
    const float* Wv = (const float*)d_in[6];
    const float* Wo = (const float*)d_in[7];
    float* out = (float*)d_out;

    float *gq, *gk, *gv;
    __half *gvals_h, *qh, *kih, *vih, *kh;
    uint32_t* ww;
    cudaGetSymbolAddress((void**)&gq, g_q);
    cudaGetSymbolAddress((void**)&gk, g_k);
    cudaGetSymbolAddress((void**)&gv, g_v);
    cudaGetSymbolAddress((void**)&gvals_h, g_vals_h);
    cudaGetSymbolAddress((void**)&qh, g_qh);
    cudaGetSymbolAddress((void**)&kih, g_kih);
    cudaGetSymbolAddress((void**)&vih, g_vih);
    cudaGetSymbolAddress((void**)&ww, g_ww);
    cudaGetSymbolAddress((void**)&kh, g_kh);

    cudaFuncSetAttribute(hgemm_v8, cudaFuncAttributeMaxDynamicSharedMemorySize,
                         GEMM_SMEM8);

    const int M = MT;  // 4096

    // 0) pre-convert inputs + weights to fp16
    dim3 pgrid(MT * CD / 4 / 256, 7);
    prep_cvt<<<pgrid, 256>>>(Q, K, V, Wq, Wk, Wv, Wo, qh, kih, vih, ww);

    // 1) QKV projections
    dim3 ggrid3(CD / BN, M / BM, 3);
    hgemm_v8<<<ggrid3, 128, GEMM_SMEM8>>>(qh, kih, vih, ww, 0, gq, gk, gv, M,
                                          CD, CD);

    // 2) rope+rms
    const int nwarps = CB * CS * CH;
    dim3 rgrid(nwarps / 8, 2);
    rope_rms_kernel<<<rgrid, 256>>>(gq, gk, kh);

    // 3) attention
    dim3 agrid(CS / 128, CB * CH);
    flash_attn_f16<<<agrid, 256>>>(gq, kh, gv, gvals_h);

    // 4) output projection
    dim3 ggrid1(CD / BN, M / BM, 1);
    hgemm_v8<<<ggrid1, 128, GEMM_SMEM8>>>(gvals_h, nullptr, nullptr, ww, 3,
                                          out, nullptr, nullptr, M, CD, CD);
}